// round 2
// baseline (speedup 1.0000x reference)
#include <cuda_runtime.h>
#include <math.h>

#define Bb 8
#define Ss 512
#define Hh 1024
#define NHh 16
#define Dd 64

// Scratch (allocation-free rule: __device__ globals)
__device__ float g_Q[Bb*NHh*Ss*Dd];   // [B,NH,S,D]
__device__ float g_K[Bb*NHh*Ss*Dd];
__device__ float g_V[Bb*NHh*Ss*Dd];
__device__ float g_A[Bb*Ss*Hh];       // attention output, [B,S,H]

// ---------------------------------------------------------------------------
// 128x128 SGEMM tile, 256 threads, 8x8 microtile (2x2 quadrants of 4x4).
// C[m,n] = sum_k X[m,k] * W[n,k]  (+ bias)  — both row-major, K contiguous.
// ---------------------------------------------------------------------------

#define TS 132   // padded smem row stride (conflict-free transposed stores)

struct Acc88 { float v[8][8]; };

__device__ __forceinline__ void gemm_mainloop(const float* __restrict__ X,
                                              const float* __restrict__ W,
                                              int m0, int n0,
                                              float* As, float* Bs,
                                              Acc88& A)
{
    const int tid  = threadIdx.x;     // 256
    const int arow = tid >> 1;        // 0..127
    const int akc  = (tid & 1) * 4;   // k sub-offset 0 or 4
    const int tx   = tid & 15;
    const int ty   = tid >> 4;

#pragma unroll
    for (int r = 0; r < 8; r++)
#pragma unroll
        for (int c = 0; c < 8; c++) A.v[r][c] = 0.f;

    for (int k0 = 0; k0 < 1024; k0 += 8) {
        float4 a = *(const float4*)&X[(size_t)(m0 + arow) * 1024 + k0 + akc];
        float4 w = *(const float4*)&W[(size_t)(n0 + arow) * 1024 + k0 + akc];
        As[(akc+0)*TS + arow] = a.x; As[(akc+1)*TS + arow] = a.y;
        As[(akc+2)*TS + arow] = a.z; As[(akc+3)*TS + arow] = a.w;
        Bs[(akc+0)*TS + arow] = w.x; Bs[(akc+1)*TS + arow] = w.y;
        Bs[(akc+2)*TS + arow] = w.z; Bs[(akc+3)*TS + arow] = w.w;
        __syncthreads();
#pragma unroll
        for (int k = 0; k < 8; k++) {
            float4 a0 = *(const float4*)&As[k*TS + ty*4];
            float4 a1 = *(const float4*)&As[k*TS + 64 + ty*4];
            float4 b0 = *(const float4*)&Bs[k*TS + tx*4];
            float4 b1 = *(const float4*)&Bs[k*TS + 64 + tx*4];
            float ra[8] = {a0.x,a0.y,a0.z,a0.w, a1.x,a1.y,a1.z,a1.w};
            float rb[8] = {b0.x,b0.y,b0.z,b0.w, b1.x,b1.y,b1.z,b1.w};
#pragma unroll
            for (int r = 0; r < 8; r++)
#pragma unroll
                for (int c = 0; c < 8; c++)
                    A.v[r][c] = fmaf(ra[r], rb[c], A.v[r][c]);
        }
        __syncthreads();
    }
}

__global__ __launch_bounds__(256, 2)
void qkv_gemm(const float* __restrict__ q_in,
              const float* __restrict__ k_in,
              const float* __restrict__ v_in,
              const float* __restrict__ Wq, const float* __restrict__ bq,
              const float* __restrict__ Wk, const float* __restrict__ bk,
              const float* __restrict__ Wv, const float* __restrict__ bv)
{
    const int which = blockIdx.z;
    const float* X    = (which == 0) ? q_in : (which == 1) ? k_in : v_in;
    const float* W    = (which == 0) ? Wq   : (which == 1) ? Wk   : Wv;
    const float* bias = (which == 0) ? bq   : (which == 1) ? bk   : bv;
    float* Out        = (which == 0) ? g_Q  : (which == 1) ? g_K  : g_V;

    const int m0 = blockIdx.x * 128;   // rows of [B*S]
    const int n0 = blockIdx.y * 128;   // cols of H

    __shared__ float As[8*TS];
    __shared__ float Bs[8*TS];
    Acc88 A;
    gemm_mainloop(X, W, m0, n0, As, Bs, A);

    const int tx = threadIdx.x & 15;
    const int ty = threadIdx.x >> 4;
    const int bidx = m0 >> 9;          // batch (128 | 512)

#pragma unroll
    for (int half = 0; half < 2; half++) {
        int nb = n0 + half*64 + tx*4;           // global col in H
        int h  = nb >> 6;                       // head
        int dcol = nb & 63;                     // col within head
        float4 bv4 = *(const float4*)&bias[nb];
#pragma unroll
        for (int r = 0; r < 8; r++) {
            int m = m0 + ((r < 4) ? (ty*4 + r) : (64 + ty*4 + r - 4));
            int s = m - bidx * Ss;
            float4 o;
            o.x = A.v[r][half*4+0] + bv4.x;
            o.y = A.v[r][half*4+1] + bv4.y;
            o.z = A.v[r][half*4+2] + bv4.z;
            o.w = A.v[r][half*4+3] + bv4.w;
            *(float4*)&Out[(((size_t)(bidx * NHh + h) * Ss + s) * Dd) + dcol] = o;
        }
    }
}

__global__ __launch_bounds__(256, 2)
void out_gemm(const float* __restrict__ Wo, const float* __restrict__ bo,
              float* __restrict__ out)
{
    const int m0 = blockIdx.x * 128;
    const int n0 = blockIdx.y * 128;

    __shared__ float As[8*TS];
    __shared__ float Bs[8*TS];
    Acc88 A;
    gemm_mainloop(g_A, Wo, m0, n0, As, Bs, A);

    const int tx = threadIdx.x & 15;
    const int ty = threadIdx.x >> 4;

#pragma unroll
    for (int half = 0; half < 2; half++) {
        int nb = n0 + half*64 + tx*4;
        float4 bv4 = *(const float4*)&bo[nb];
#pragma unroll
        for (int r = 0; r < 8; r++) {
            int m = m0 + ((r < 4) ? (ty*4 + r) : (64 + ty*4 + r - 4));
            float4 o;
            o.x = A.v[r][half*4+0] + bv4.x;
            o.y = A.v[r][half*4+1] + bv4.y;
            o.z = A.v[r][half*4+2] + bv4.z;
            o.w = A.v[r][half*4+3] + bv4.w;
            *(float4*)&out[(size_t)m * Hh + nb] = o;
        }
    }
}

// ---------------------------------------------------------------------------
// Attention kernel: one block per (b, h, 32-query tile).
// Full 32x512 score tile in dynamic smem; two-pass softmax; fused
// large/sim/top modification; PV GEMM.
// ---------------------------------------------------------------------------

#define SC_STRIDE 513
#define QS_STRIDE 34
#define KV_STRIDE 68
#define SMEM_FLOATS (32 * SC_STRIDE + 64 * QS_STRIDE + 64 * KV_STRIDE)

__global__ void attn_kernel(const float* __restrict__ mask,
                            const int* __restrict__ lena,
                            const float* __restrict__ kg,
                            const float* __restrict__ hy,
                            const int* __restrict__ layer_p)
{
    extern __shared__ float sm[];
    float* sc = sm;                       // [32][513]
    float* Qs = sm + 32 * SC_STRIDE;      // [d][q] stride 34
    float* KV = Qs + 64 * QS_STRIDE;      // K tile [d][k] / V tile [k][d], stride 68

    const int bh = blockIdx.y;            // 0..127
    const int b  = bh >> 4;
    const int h  = bh & 15;
    const int q0 = blockIdx.x * 32;
    const int tid = threadIdx.x;          // 256

    const int layer = layer_p[0];
    const float c0 = hy[layer * 3 + 0];
    const float c1 = hy[layer * 3 + 1];
    const float cc = hy[layer * 3 + 2];
    const int   l  = lena[b];

    const float* Qp = g_Q + (size_t)bh * Ss * Dd;
    const float* Kp = g_K + (size_t)bh * Ss * Dd;
    const float* Vp = g_V + (size_t)bh * Ss * Dd;

    // ---- load Q tile transposed: Qs[d][q] ----
    {
        const int dg = tid & 15;          // float4 group of d
        const int qq = tid >> 4;          // 0..15
#pragma unroll
        for (int i = 0; i < 2; i++) {
            int q = qq + 16 * i;
            float4 v = *(const float4*)&Qp[(size_t)(q0 + q) * Dd + dg * 4];
            Qs[(dg*4+0) * QS_STRIDE + q] = v.x;
            Qs[(dg*4+1) * QS_STRIDE + q] = v.y;
            Qs[(dg*4+2) * QS_STRIDE + q] = v.z;
            Qs[(dg*4+3) * QS_STRIDE + q] = v.w;
        }
    }
    __syncthreads();

    // ---- scores: sc[q][k] = (Q K^T)/8 ----
    const int qi2 = tid & 15;             // q pair: q = 2*qi2 + {0,1}
    const int grp = tid >> 4;             // 0..15
    for (int kt = 0; kt < 8; kt++) {
        // load K tile transposed: KV[d][k], k in [kt*64, kt*64+64)
        {
            const int dg = tid & 15;
            const int kk = tid >> 4;
#pragma unroll
            for (int i = 0; i < 4; i++) {
                int k = kk + 16 * i;
                float4 v = *(const float4*)&Kp[(size_t)(kt * 64 + k) * Dd + dg * 4];
                KV[(dg*4+0) * KV_STRIDE + k] = v.x;
                KV[(dg*4+1) * KV_STRIDE + k] = v.y;
                KV[(dg*4+2) * KV_STRIDE + k] = v.z;
                KV[(dg*4+3) * KV_STRIDE + k] = v.w;
            }
        }
        __syncthreads();

        float a00=0,a01=0,a02=0,a03=0,a10=0,a11=0,a12=0,a13=0;
#pragma unroll
        for (int d = 0; d < 64; d++) {
            float2 qv = *(const float2*)&Qs[d * QS_STRIDE + qi2 * 2];
            float4 kv = *(const float4*)&KV[d * KV_STRIDE + grp * 4];
            a00 = fmaf(qv.x, kv.x, a00); a01 = fmaf(qv.x, kv.y, a01);
            a02 = fmaf(qv.x, kv.z, a02); a03 = fmaf(qv.x, kv.w, a03);
            a10 = fmaf(qv.y, kv.x, a10); a11 = fmaf(qv.y, kv.y, a11);
            a12 = fmaf(qv.y, kv.z, a12); a13 = fmaf(qv.y, kv.w, a13);
        }
        int kb = kt * 64 + grp * 4;
        float* r0 = &sc[(qi2*2  ) * SC_STRIDE + kb];
        float* r1 = &sc[(qi2*2+1) * SC_STRIDE + kb];
        r0[0]=a00*0.125f; r0[1]=a01*0.125f; r0[2]=a02*0.125f; r0[3]=a03*0.125f;
        r1[0]=a10*0.125f; r1[1]=a11*0.125f; r1[2]=a12*0.125f; r1[3]=a13*0.125f;
        __syncthreads();
    }

    // ---- add mask ----
    for (int idx = tid; idx < 32 * 512; idx += 256) {
        int q = idx >> 9, k = idx & 511;
        sc[q * SC_STRIDE + k] += mask[((size_t)b * Ss + (q0 + q)) * Ss + k];
    }
    __syncthreads();

    // ---- softmax + modification (8 lanes per row) ----
    {
        const int row = tid >> 3;         // 0..31
        const int sub = tid & 7;
        float* rowp = &sc[row * SC_STRIDE];

        float mx = -1e30f;
        for (int k = sub; k < 512; k += 8) mx = fmaxf(mx, rowp[k]);
        mx = fmaxf(mx, __shfl_xor_sync(0xffffffffu, mx, 1));
        mx = fmaxf(mx, __shfl_xor_sync(0xffffffffu, mx, 2));
        mx = fmaxf(mx, __shfl_xor_sync(0xffffffffu, mx, 4));

        float sum = 0.f;
        for (int k = sub; k < 512; k += 8) {
            float e = __expf(rowp[k] - mx);
            rowp[k] = e;
            sum += e;
        }
        sum += __shfl_xor_sync(0xffffffffu, sum, 1);
        sum += __shfl_xor_sync(0xffffffffu, sum, 2);
        sum += __shfl_xor_sync(0xffffffffu, sum, 4);
        float inv = 1.f / sum;

        const int qg = q0 + row;
        const bool rowa_q = (qg >= 1) && (qg < l - 1);
        const bool cola_q = (qg >= l) && (qg < Ss - 1);
        const float* simp = &kg[(((size_t)b * 2 + 0) * Ss + qg) * Ss];
        const float* topp = &kg[(((size_t)b * 2 + 1) * Ss + qg) * Ss];
        for (int k = sub; k < 512; k += 8) {
            bool rowa_k = (k >= 1) && (k < l - 1);
            bool cola_k = (k >= l) && (k < Ss - 1);
            bool big = (rowa_q && cola_k) || (rowa_k && cola_q);
            float lf = big ? cc : 1.0f;
            rowp[k] = rowp[k] * inv * lf + c0 * simp[k] + c1 * topp[k];
        }
    }
    __syncthreads();

    // ---- PV: out[q][d] = sum_k sc[q][k] * V[k][d] ----
    float o00=0,o01=0,o02=0,o03=0,o10=0,o11=0,o12=0,o13=0;
    for (int kt = 0; kt < 8; kt++) {
        // load V tile: KV[k][d], k in [kt*64, ..)
        {
            const int dg = tid & 15;
            const int kk = tid >> 4;
#pragma unroll
            for (int i = 0; i < 4; i++) {
                int k = kk + 16 * i;
                float4 v = *(const float4*)&Vp[(size_t)(kt * 64 + k) * Dd + dg * 4];
                *(float4*)&KV[k * KV_STRIDE + dg * 4] = v;
            }
        }
        __syncthreads();
#pragma unroll 8
        for (int kk = 0; kk < 64; kk++) {
            int k = kt * 64 + kk;
            float p0 = sc[(qi2*2  ) * SC_STRIDE + k];
            float p1 = sc[(qi2*2+1) * SC_STRIDE + k];
            float4 vv = *(const float4*)&KV[kk * KV_STRIDE + grp * 4];
            o00 = fmaf(p0, vv.x, o00); o01 = fmaf(p0, vv.y, o01);
            o02 = fmaf(p0, vv.z, o02); o03 = fmaf(p0, vv.w, o03);
            o10 = fmaf(p1, vv.x, o10); o11 = fmaf(p1, vv.y, o11);
            o12 = fmaf(p1, vv.z, o12); o13 = fmaf(p1, vv.w, o13);
        }
        __syncthreads();
    }

    // write to g_A [B,S,H]: row = b*S + q0 + q, col = h*64 + grp*4
    {
        size_t base0 = ((size_t)b * Ss + q0 + qi2 * 2    ) * Hh + h * 64 + grp * 4;
        size_t base1 = ((size_t)b * Ss + q0 + qi2 * 2 + 1) * Hh + h * 64 + grp * 4;
        float4 w0 = {o00, o01, o02, o03};
        float4 w1 = {o10, o11, o12, o13};
        *(float4*)&g_A[base0] = w0;
        *(float4*)&g_A[base1] = w1;
    }
}

// ---------------------------------------------------------------------------
// Launch
// ---------------------------------------------------------------------------

extern "C" void kernel_launch(void* const* d_in, const int* in_sizes, int n_in,
                              void* d_out, int out_size)
{
    const float* q_in  = (const float*)d_in[0];
    const float* k_in  = (const float*)d_in[1];
    const float* v_in  = (const float*)d_in[2];
    const float* mask  = (const float*)d_in[3];
    const int*   lena  = (const int*)  d_in[4];
    const float* kg    = (const float*)d_in[5];
    const float* hy    = (const float*)d_in[6];
    const int*   layer = (const int*)  d_in[7];
    const float* Wq    = (const float*)d_in[8];
    const float* bq    = (const float*)d_in[9];
    const float* Wk    = (const float*)d_in[10];
    const float* bk    = (const float*)d_in[11];
    const float* Wv    = (const float*)d_in[12];
    const float* bv    = (const float*)d_in[13];
    const float* Wo    = (const float*)d_in[14];
    const float* bo    = (const float*)d_in[15];
    float* out = (float*)d_out;

    // QKV projections
    {
        dim3 grid(4096 / 128, 1024 / 128, 3);
        qkv_gemm<<<grid, 256>>>(q_in, k_in, v_in, Wq, bq, Wk, bk, Wv, bv);
    }

    // Attention
    {
        const int smem_bytes = SMEM_FLOATS * (int)sizeof(float);   // ~91.8 KB
        cudaFuncSetAttribute(attn_kernel,
                             cudaFuncAttributeMaxDynamicSharedMemorySize, smem_bytes);
        dim3 grid(Ss / 32, Bb * NHh, 1);
        attn_kernel<<<grid, 256, smem_bytes>>>(mask, lena, kg, hy, layer);
    }

    // Output projection
    {
        dim3 grid(4096 / 128, 1024 / 128, 1);
        out_gemm<<<grid, 256>>>(Wo, bo, out);
    }
}

// round 5
// speedup vs baseline: 1.5588x; 1.5588x over previous
#include <cuda_runtime.h>
#include <cuda_bf16.h>
#include <stdint.h>
#include <math.h>

#define Bb 8
#define Ss 512
#define Hh 1024
#define NHh 16
#define Dd 64

// ---------------------------------------------------------------------------
// Scratch (allocation-free rule: __device__ globals)
// ---------------------------------------------------------------------------
__device__ float g_Q[Bb*NHh*Ss*Dd];   // [B,NH,S,D] fp32
__device__ float g_K[Bb*NHh*Ss*Dd];
__device__ float g_V[Bb*NHh*Ss*Dd];
__device__ float g_A[Bb*Ss*Hh];       // attention output, [B,S,H] fp32

// bf16 hi/lo splits
__device__ __nv_bfloat16 s_xh[3][4096*1024];   // q,k,v inputs
__device__ __nv_bfloat16 s_xl[3][4096*1024];
__device__ __nv_bfloat16 s_wh[4][1024*1024];   // Wq,Wk,Wv,Wo
__device__ __nv_bfloat16 s_wl[4][1024*1024];
__device__ __nv_bfloat16 s_ah[4096*1024];      // attention out split
__device__ __nv_bfloat16 s_al[4096*1024];

// ---------------------------------------------------------------------------
// Baseline-PTX tensor core helpers (no 'a'-gated instructions!)
// ---------------------------------------------------------------------------
__device__ __forceinline__ uint32_t smem_u32(const void* p) {
    uint32_t a;
    asm("{ .reg .u64 t; cvta.to.shared.u64 t, %1; cvt.u32.u64 %0, t; }" : "=r"(a) : "l"(p));
    return a;
}

__device__ __forceinline__ void mma16816(float* c,
    uint32_t a0, uint32_t a1, uint32_t a2, uint32_t a3,
    uint32_t b0, uint32_t b1)
{
    asm volatile(
        "mma.sync.aligned.m16n8k16.row.col.f32.bf16.bf16.f32 "
        "{%0,%1,%2,%3}, {%4,%5,%6,%7}, {%8,%9}, {%0,%1,%2,%3};"
        : "+f"(c[0]), "+f"(c[1]), "+f"(c[2]), "+f"(c[3])
        : "r"(a0), "r"(a1), "r"(a2), "r"(a3), "r"(b0), "r"(b1));
}

__device__ __forceinline__ void ldsm_x4(uint32_t& r0, uint32_t& r1,
                                        uint32_t& r2, uint32_t& r3, uint32_t addr)
{
    asm volatile("ldmatrix.sync.aligned.m8n8.x4.shared.b16 {%0,%1,%2,%3}, [%4];"
                 : "=r"(r0), "=r"(r1), "=r"(r2), "=r"(r3) : "r"(addr));
}

__device__ __forceinline__ void cp_async16(uint32_t saddr, const void* gaddr) {
    asm volatile("cp.async.cg.shared.global [%0], [%1], 16;" :: "r"(saddr), "l"(gaddr));
}
__device__ __forceinline__ void cp_commit() {
    asm volatile("cp.async.commit_group;" ::: "memory");
}
template <int N>
__device__ __forceinline__ void cp_wait() {
    asm volatile("cp.async.wait_group %0;" :: "n"(N) : "memory");
}

// ---------------------------------------------------------------------------
// fp32 -> (hi,lo) bf16 split. which: 0..2 = q/k/v inputs, 3..6 = Wq/Wk/Wv/Wo,
// 7 = g_A (src ignored).
// ---------------------------------------------------------------------------
__global__ __launch_bounds__(256)
void cvt_hilo(const float* __restrict__ src, int which, int n4)
{
    __nv_bfloat16* hi;
    __nv_bfloat16* lo;
    if (which < 3)       { hi = s_xh[which];     lo = s_xl[which]; }
    else if (which < 7)  { hi = s_wh[which - 3]; lo = s_wl[which - 3]; }
    else                 { hi = s_ah; lo = s_al; src = g_A; }

    int i = blockIdx.x * blockDim.x + threadIdx.x;
    if (i >= n4) return;
    float4 v = ((const float4*)src)[i];
    float f[4] = {v.x, v.y, v.z, v.w};
    __nv_bfloat16 h[4], l[4];
#pragma unroll
    for (int j = 0; j < 4; j++) {
        h[j] = __float2bfloat16(f[j]);
        l[j] = __float2bfloat16(f[j] - __bfloat162float(h[j]));
    }
    ((uint2*)hi)[i] = *(uint2*)h;
    ((uint2*)lo)[i] = *(uint2*)l;
}

// ---------------------------------------------------------------------------
// HMMA GEMM: C[4096x1024] = X @ W^T (+bias), bf16 3-term compensation.
// Block tile 128x128, BK=32, 8 warps (32x64 each), 2-stage cp.async pipeline.
// SMEM tile layout: row stride 80 B (64 B data + 16 pad -> conflict-free ldmatrix).
// Stage = [Ah | Al | Bh | Bl], each 128*80 = 10240 B -> 40960 B; x2 stages.
// ---------------------------------------------------------------------------
#define T_ROWB 80
#define TILE_B (128 * T_ROWB)       // 10240
#define STAGE_B (4 * TILE_B)        // 40960
#define GEMM_SMEM (2 * STAGE_B)     // 81920

__device__ __forceinline__ void stage_load(
    uint32_t smb, int buf, int k0,
    const __nv_bfloat16* Ah, const __nv_bfloat16* Al,
    const __nv_bfloat16* Bh, const __nv_bfloat16* Bl,
    int m0, int n0, int tid)
{
    const __nv_bfloat16* srcs[4] = {Ah, Al, Bh, Bl};
    const int rb[4] = {m0, m0, n0, n0};
    uint32_t sb = smb + buf * STAGE_B;
#pragma unroll
    for (int t = 0; t < 4; t++) {
#pragma unroll
        for (int i = 0; i < 2; i++) {
            int c = tid + i * 256;        // 0..511
            int r = c >> 2;               // 0..127
            int kc = c & 3;               // 16B chunk
            const void* g = srcs[t] + (size_t)(rb[t] + r) * 1024 + k0 + kc * 8;
            cp_async16(sb + t * TILE_B + r * T_ROWB + kc * 16, g);
        }
    }
}

__device__ __forceinline__ void gemm_hmma_body(
    const __nv_bfloat16* __restrict__ Ah, const __nv_bfloat16* __restrict__ Al,
    const __nv_bfloat16* __restrict__ Bh, const __nv_bfloat16* __restrict__ Bl,
    const float* __restrict__ bias, float* __restrict__ outp, int mode,
    uint8_t* dynsm)
{
    const uint32_t smb = smem_u32(dynsm);
    const int tid  = threadIdx.x;
    const int wid  = tid >> 5;
    const int lane = tid & 31;
    const int wm   = wid & 3;        // 4 warps in m
    const int wn   = wid >> 2;       // 2 warps in n
    const int m0   = blockIdx.x * 128;
    const int n0   = blockIdx.y * 128;

    float acc[2][8][4];
#pragma unroll
    for (int mt = 0; mt < 2; mt++)
#pragma unroll
        for (int nt = 0; nt < 8; nt++)
#pragma unroll
            for (int j = 0; j < 4; j++) acc[mt][nt][j] = 0.f;

    // ldmatrix lane-address components
    const int a_row = (lane & 15);                 // + mt*16 + wm*32
    const int a_col = (lane >> 4) * 16;            // + kh*32
    const int b_row = (lane & 7) + ((lane >> 4) & 1) * 8;   // + p*16 + wn*64
    const int b_col = ((lane >> 3) & 1) * 16;               // + kh*32

    stage_load(smb, 0, 0, Ah, Al, Bh, Bl, m0, n0, tid);
    cp_commit();

    const int NS = 1024 / 32;
    for (int s = 0; s < NS; s++) {
        if (s + 1 < NS) {
            stage_load(smb, (s + 1) & 1, (s + 1) * 32, Ah, Al, Bh, Bl, m0, n0, tid);
            cp_commit();
            cp_wait<1>();
        } else {
            cp_wait<0>();
        }
        __syncthreads();

        const uint32_t sb = smb + (s & 1) * STAGE_B;
        const uint32_t sAh = sb;
        const uint32_t sAl = sb + TILE_B;
        const uint32_t sBh = sb + 2 * TILE_B;
        const uint32_t sBl = sb + 3 * TILE_B;

#pragma unroll
        for (int kh = 0; kh < 2; kh++) {
            const int kb = kh * 32;
            uint32_t b[8][2];
            // pass 1: B-hi; A-hi and A-lo MMAs
#pragma unroll
            for (int p = 0; p < 4; p++) {
                uint32_t addr = sBh + (uint32_t)(wn * 64 + p * 16 + b_row) * T_ROWB + kb + b_col;
                ldsm_x4(b[2*p][0], b[2*p][1], b[2*p+1][0], b[2*p+1][1], addr);
            }
#pragma unroll
            for (int mt = 0; mt < 2; mt++) {
                uint32_t ah[4], al[4];
                uint32_t ra = (uint32_t)(wm * 32 + mt * 16 + a_row) * T_ROWB + kb + a_col;
                ldsm_x4(ah[0], ah[1], ah[2], ah[3], sAh + ra);
                ldsm_x4(al[0], al[1], al[2], al[3], sAl + ra);
#pragma unroll
                for (int nt = 0; nt < 8; nt++) {
                    mma16816(acc[mt][nt], ah[0], ah[1], ah[2], ah[3], b[nt][0], b[nt][1]);
                    mma16816(acc[mt][nt], al[0], al[1], al[2], al[3], b[nt][0], b[nt][1]);
                }
            }
            // pass 2: B-lo; A-hi MMAs
#pragma unroll
            for (int p = 0; p < 4; p++) {
                uint32_t addr = sBl + (uint32_t)(wn * 64 + p * 16 + b_row) * T_ROWB + kb + b_col;
                ldsm_x4(b[2*p][0], b[2*p][1], b[2*p+1][0], b[2*p+1][1], addr);
            }
#pragma unroll
            for (int mt = 0; mt < 2; mt++) {
                uint32_t ah[4];
                uint32_t ra = (uint32_t)(wm * 32 + mt * 16 + a_row) * T_ROWB + kb + a_col;
                ldsm_x4(ah[0], ah[1], ah[2], ah[3], sAh + ra);
#pragma unroll
                for (int nt = 0; nt < 8; nt++)
                    mma16816(acc[mt][nt], ah[0], ah[1], ah[2], ah[3], b[nt][0], b[nt][1]);
            }
        }
        __syncthreads();
    }

    // Epilogue: fragment rows g,g+8; cols (lane&3)*2
    const int g  = lane >> 2;
    const int cq = (lane & 3) * 2;
#pragma unroll
    for (int mt = 0; mt < 2; mt++) {
#pragma unroll
        for (int nt = 0; nt < 8; nt++) {
            int col  = n0 + wn * 64 + nt * 8 + cq;
            int row0 = m0 + wm * 32 + mt * 16 + g;
            float bx = bias[col], by = bias[col + 1];
            float2 v0 = {acc[mt][nt][0] + bx, acc[mt][nt][1] + by};
            float2 v1 = {acc[mt][nt][2] + bx, acc[mt][nt][3] + by};
            if (mode == 0) {
                int bidx = row0 >> 9;
                int s0 = row0 & 511;
                int h = col >> 6, d = col & 63;
                float* base = &outp[(((size_t)(bidx * NHh + h) * Ss)) * Dd + d];
                *(float2*)&base[(size_t)s0 * Dd] = v0;
                *(float2*)&base[(size_t)(s0 + 8) * Dd] = v1;
            } else {
                *(float2*)&outp[(size_t)row0 * Hh + col] = v0;
                *(float2*)&outp[(size_t)(row0 + 8) * Hh + col] = v1;
            }
        }
    }
}

__global__ __launch_bounds__(256, 2)
void gemm_qkv_tc(const float* __restrict__ bq, const float* __restrict__ bk,
                 const float* __restrict__ bv)
{
    extern __shared__ uint8_t dynsm[];
    const int which = blockIdx.z;
    const float* bias = (which == 0) ? bq : (which == 1) ? bk : bv;
    float* outp = (which == 0) ? g_Q : (which == 1) ? g_K : g_V;
    gemm_hmma_body(s_xh[which], s_xl[which], s_wh[which], s_wl[which],
                   bias, outp, 0, dynsm);
}

__global__ __launch_bounds__(256, 2)
void gemm_out_tc(const float* __restrict__ bo, float* __restrict__ out)
{
    extern __shared__ uint8_t dynsm[];
    gemm_hmma_body(s_ah, s_al, s_wh[3], s_wl[3], bo, out, 1, dynsm);
}

// ---------------------------------------------------------------------------
// Attention kernel (unchanged from passing baseline)
// ---------------------------------------------------------------------------
#define SC_STRIDE 513
#define QS_STRIDE 34
#define KV_STRIDE 68
#define SMEM_FLOATS (32 * SC_STRIDE + 64 * QS_STRIDE + 64 * KV_STRIDE)

__global__ void attn_kernel(const float* __restrict__ mask,
                            const int* __restrict__ lena,
                            const float* __restrict__ kg,
                            const float* __restrict__ hy,
                            const int* __restrict__ layer_p)
{
    extern __shared__ float sm[];
    float* sc = sm;                       // [32][513]
    float* Qs = sm + 32 * SC_STRIDE;      // [d][q] stride 34
    float* KV = Qs + 64 * QS_STRIDE;      // K tile [d][k] / V tile [k][d], stride 68

    const int bh = blockIdx.y;
    const int b  = bh >> 4;
    const int h  = bh & 15;
    const int q0 = blockIdx.x * 32;
    const int tid = threadIdx.x;

    const int layer = layer_p[0];
    const float c0 = hy[layer * 3 + 0];
    const float c1 = hy[layer * 3 + 1];
    const float cc = hy[layer * 3 + 2];
    const int   l  = lena[b];

    const float* Qp = g_Q + (size_t)bh * Ss * Dd;
    const float* Kp = g_K + (size_t)bh * Ss * Dd;
    const float* Vp = g_V + (size_t)bh * Ss * Dd;

    {
        const int dg = tid & 15;
        const int qq = tid >> 4;
#pragma unroll
        for (int i = 0; i < 2; i++) {
            int q = qq + 16 * i;
            float4 v = *(const float4*)&Qp[(size_t)(q0 + q) * Dd + dg * 4];
            Qs[(dg*4+0) * QS_STRIDE + q] = v.x;
            Qs[(dg*4+1) * QS_STRIDE + q] = v.y;
            Qs[(dg*4+2) * QS_STRIDE + q] = v.z;
            Qs[(dg*4+3) * QS_STRIDE + q] = v.w;
        }
    }
    __syncthreads();

    const int qi2 = tid & 15;
    const int grp = tid >> 4;
    for (int kt = 0; kt < 8; kt++) {
        {
            const int dg = tid & 15;
            const int kk = tid >> 4;
#pragma unroll
            for (int i = 0; i < 4; i++) {
                int k = kk + 16 * i;
                float4 v = *(const float4*)&Kp[(size_t)(kt * 64 + k) * Dd + dg * 4];
                KV[(dg*4+0) * KV_STRIDE + k] = v.x;
                KV[(dg*4+1) * KV_STRIDE + k] = v.y;
                KV[(dg*4+2) * KV_STRIDE + k] = v.z;
                KV[(dg*4+3) * KV_STRIDE + k] = v.w;
            }
        }
        __syncthreads();

        float a00=0,a01=0,a02=0,a03=0,a10=0,a11=0,a12=0,a13=0;
#pragma unroll
        for (int d = 0; d < 64; d++) {
            float2 qv = *(const float2*)&Qs[d * QS_STRIDE + qi2 * 2];
            float4 kv = *(const float4*)&KV[d * KV_STRIDE + grp * 4];
            a00 = fmaf(qv.x, kv.x, a00); a01 = fmaf(qv.x, kv.y, a01);
            a02 = fmaf(qv.x, kv.z, a02); a03 = fmaf(qv.x, kv.w, a03);
            a10 = fmaf(qv.y, kv.x, a10); a11 = fmaf(qv.y, kv.y, a11);
            a12 = fmaf(qv.y, kv.z, a12); a13 = fmaf(qv.y, kv.w, a13);
        }
        int kb = kt * 64 + grp * 4;
        float* r0 = &sc[(qi2*2  ) * SC_STRIDE + kb];
        float* r1 = &sc[(qi2*2+1) * SC_STRIDE + kb];
        r0[0]=a00*0.125f; r0[1]=a01*0.125f; r0[2]=a02*0.125f; r0[3]=a03*0.125f;
        r1[0]=a10*0.125f; r1[1]=a11*0.125f; r1[2]=a12*0.125f; r1[3]=a13*0.125f;
        __syncthreads();
    }

    for (int idx = tid; idx < 32 * 512; idx += 256) {
        int q = idx >> 9, k = idx & 511;
        sc[q * SC_STRIDE + k] += mask[((size_t)b * Ss + (q0 + q)) * Ss + k];
    }
    __syncthreads();

    {
        const int row = tid >> 3;
        const int sub = tid & 7;
        float* rowp = &sc[row * SC_STRIDE];

        float mx = -1e30f;
        for (int k = sub; k < 512; k += 8) mx = fmaxf(mx, rowp[k]);
        mx = fmaxf(mx, __shfl_xor_sync(0xffffffffu, mx, 1));
        mx = fmaxf(mx, __shfl_xor_sync(0xffffffffu, mx, 2));
        mx = fmaxf(mx, __shfl_xor_sync(0xffffffffu, mx, 4));

        float sum = 0.f;
        for (int k = sub; k < 512; k += 8) {
            float e = __expf(rowp[k] - mx);
            rowp[k] = e;
            sum += e;
        }
        sum += __shfl_xor_sync(0xffffffffu, sum, 1);
        sum += __shfl_xor_sync(0xffffffffu, sum, 2);
        sum += __shfl_xor_sync(0xffffffffu, sum, 4);
        float inv = 1.f / sum;

        const int qg = q0 + row;
        const bool rowa_q = (qg >= 1) && (qg < l - 1);
        const bool cola_q = (qg >= l) && (qg < Ss - 1);
        const float* simp = &kg[(((size_t)b * 2 + 0) * Ss + qg) * Ss];
        const float* topp = &kg[(((size_t)b * 2 + 1) * Ss + qg) * Ss];
        for (int k = sub; k < 512; k += 8) {
            bool rowa_k = (k >= 1) && (k < l - 1);
            bool cola_k = (k >= l) && (k < Ss - 1);
            bool big = (rowa_q && cola_k) || (rowa_k && cola_q);
            float lf = big ? cc : 1.0f;
            rowp[k] = rowp[k] * inv * lf + c0 * simp[k] + c1 * topp[k];
        }
    }
    __syncthreads();

    float o00=0,o01=0,o02=0,o03=0,o10=0,o11=0,o12=0,o13=0;
    for (int kt = 0; kt < 8; kt++) {
        {
            const int dg = tid & 15;
            const int kk = tid >> 4;
#pragma unroll
            for (int i = 0; i < 4; i++) {
                int k = kk + 16 * i;
                float4 v = *(const float4*)&Vp[(size_t)(kt * 64 + k) * Dd + dg * 4];
                *(float4*)&KV[k * KV_STRIDE + dg * 4] = v;
            }
        }
        __syncthreads();
#pragma unroll 8
        for (int kk = 0; kk < 64; kk++) {
            int k = kt * 64 + kk;
            float p0 = sc[(qi2*2  ) * SC_STRIDE + k];
            float p1 = sc[(qi2*2+1) * SC_STRIDE + k];
            float4 vv = *(const float4*)&KV[kk * KV_STRIDE + grp * 4];
            o00 = fmaf(p0, vv.x, o00); o01 = fmaf(p0, vv.y, o01);
            o02 = fmaf(p0, vv.z, o02); o03 = fmaf(p0, vv.w, o03);
            o10 = fmaf(p1, vv.x, o10); o11 = fmaf(p1, vv.y, o11);
            o12 = fmaf(p1, vv.z, o12); o13 = fmaf(p1, vv.w, o13);
        }
        __syncthreads();
    }

    {
        size_t base0 = ((size_t)b * Ss + q0 + qi2 * 2    ) * Hh + h * 64 + grp * 4;
        size_t base1 = ((size_t)b * Ss + q0 + qi2 * 2 + 1) * Hh + h * 64 + grp * 4;
        float4 w0 = {o00, o01, o02, o03};
        float4 w1 = {o10, o11, o12, o13};
        *(float4*)&g_A[base0] = w0;
        *(float4*)&g_A[base1] = w1;
    }
}

// ---------------------------------------------------------------------------
// Launch
// ---------------------------------------------------------------------------
extern "C" void kernel_launch(void* const* d_in, const int* in_sizes, int n_in,
                              void* d_out, int out_size)
{
    const float* q_in  = (const float*)d_in[0];
    const float* k_in  = (const float*)d_in[1];
    const float* v_in  = (const float*)d_in[2];
    const float* mask  = (const float*)d_in[3];
    const int*   lena  = (const int*)  d_in[4];
    const float* kg    = (const float*)d_in[5];
    const float* hy    = (const float*)d_in[6];
    const int*   layer = (const int*)  d_in[7];
    const float* Wq    = (const float*)d_in[8];
    const float* bq    = (const float*)d_in[9];
    const float* Wk    = (const float*)d_in[10];
    const float* bk    = (const float*)d_in[11];
    const float* Wv    = (const float*)d_in[12];
    const float* bv    = (const float*)d_in[13];
    const float* Wo    = (const float*)d_in[14];
    const float* bo    = (const float*)d_in[15];
    float* out = (float*)d_out;

    cudaFuncSetAttribute(gemm_qkv_tc, cudaFuncAttributeMaxDynamicSharedMemorySize, GEMM_SMEM);
    cudaFuncSetAttribute(gemm_out_tc, cudaFuncAttributeMaxDynamicSharedMemorySize, GEMM_SMEM);
    cudaFuncSetAttribute(attn_kernel, cudaFuncAttributeMaxDynamicSharedMemorySize,
                         SMEM_FLOATS * (int)sizeof(float));

    // Split inputs + weights to bf16 hi/lo
    {
        const int n4x = 4096 * 1024 / 4;
        cvt_hilo<<<n4x / 256, 256>>>(q_in, 0, n4x);
        cvt_hilo<<<n4x / 256, 256>>>(k_in, 1, n4x);
        cvt_hilo<<<n4x / 256, 256>>>(v_in, 2, n4x);
        const int n4w = 1024 * 1024 / 4;
        cvt_hilo<<<n4w / 256, 256>>>(Wq, 3, n4w);
        cvt_hilo<<<n4w / 256, 256>>>(Wk, 4, n4w);
        cvt_hilo<<<n4w / 256, 256>>>(Wv, 5, n4w);
        cvt_hilo<<<n4w / 256, 256>>>(Wv, 5, n4w);
        cvt_hilo<<<n4w / 256, 256>>>(Wo, 6, n4w);
    }

    // QKV projections on tensor cores (HMMA)
    {
        dim3 grid(4096 / 128, 1024 / 128, 3);
        gemm_qkv_tc<<<grid, 256, GEMM_SMEM>>>(bq, bk, bv);
    }

    // Attention
    {
        dim3 grid(Ss / 32, Bb * NHh, 1);
        attn_kernel<<<grid, 256, SMEM_FLOATS * (int)sizeof(float)>>>(mask, lena, kg, hy, layer);
    }

    // Split attention output, then output projection on tensor cores
    {
        const int n4a = 4096 * 1024 / 4;
        cvt_hilo<<<n4a / 256, 256>>>(nullptr, 7, n4a);
        dim3 grid(4096 / 128, 1024 / 128, 1);
        gemm_out_tc<<<grid, 256, GEMM_SMEM>>>(bo, out);
    }
}

// round 8
// speedup vs baseline: 1.8280x; 1.1727x over previous
#include <cuda_runtime.h>
#include <cuda_bf16.h>
#include <stdint.h>
#include <math.h>

#define Bb 8
#define Ss 512
#define Hh 1024
#define NHh 16
#define Dd 64

// ---------------------------------------------------------------------------
// Scratch (allocation-free rule: __device__ globals)
// ---------------------------------------------------------------------------
// bf16 hi/lo splits of GEMM inputs
__device__ __nv_bfloat16 s_xh[3][4096*1024];   // q,k,v inputs
__device__ __nv_bfloat16 s_xl[3][4096*1024];
__device__ __nv_bfloat16 s_wh[4][1024*1024];   // Wq,Wk,Wv,Wo
__device__ __nv_bfloat16 s_wl[4][1024*1024];
// projection outputs, head-major [B,NH,S,D], bf16 hi/lo
__device__ __nv_bfloat16 a_qh[Bb*NHh*Ss*Dd];
__device__ __nv_bfloat16 a_ql[Bb*NHh*Ss*Dd];
__device__ __nv_bfloat16 a_kh[Bb*NHh*Ss*Dd];
__device__ __nv_bfloat16 a_kl[Bb*NHh*Ss*Dd];
__device__ __nv_bfloat16 a_vh[Bb*NHh*Ss*Dd];
__device__ __nv_bfloat16 a_vl[Bb*NHh*Ss*Dd];
// attention output [B,S,H], bf16 hi/lo (A operand of out_gemm)
__device__ __nv_bfloat16 s_ah[4096*1024];
__device__ __nv_bfloat16 s_al[4096*1024];

// ---------------------------------------------------------------------------
// Baseline-PTX tensor core helpers (no 'a'-gated instructions)
// ---------------------------------------------------------------------------
__device__ __forceinline__ uint32_t smem_u32(const void* p) {
    uint32_t a;
    asm("{ .reg .u64 t; cvta.to.shared.u64 t, %1; cvt.u32.u64 %0, t; }" : "=r"(a) : "l"(p));
    return a;
}

__device__ __forceinline__ void mma16816(float* c,
    uint32_t a0, uint32_t a1, uint32_t a2, uint32_t a3,
    uint32_t b0, uint32_t b1)
{
    asm volatile(
        "mma.sync.aligned.m16n8k16.row.col.f32.bf16.bf16.f32 "
        "{%0,%1,%2,%3}, {%4,%5,%6,%7}, {%8,%9}, {%0,%1,%2,%3};"
        : "+f"(c[0]), "+f"(c[1]), "+f"(c[2]), "+f"(c[3])
        : "r"(a0), "r"(a1), "r"(a2), "r"(a3), "r"(b0), "r"(b1));
}

__device__ __forceinline__ void ldsm_x4(uint32_t& r0, uint32_t& r1,
                                        uint32_t& r2, uint32_t& r3, uint32_t addr)
{
    asm volatile("ldmatrix.sync.aligned.m8n8.x4.shared.b16 {%0,%1,%2,%3}, [%4];"
                 : "=r"(r0), "=r"(r1), "=r"(r2), "=r"(r3) : "r"(addr));
}

__device__ __forceinline__ void ldsm_x4_t(uint32_t& r0, uint32_t& r1,
                                          uint32_t& r2, uint32_t& r3, uint32_t addr)
{
    asm volatile("ldmatrix.sync.aligned.m8n8.x4.trans.shared.b16 {%0,%1,%2,%3}, [%4];"
                 : "=r"(r0), "=r"(r1), "=r"(r2), "=r"(r3) : "r"(addr));
}

__device__ __forceinline__ void cp_async16(uint32_t saddr, const void* gaddr) {
    asm volatile("cp.async.cg.shared.global [%0], [%1], 16;" :: "r"(saddr), "l"(gaddr));
}
__device__ __forceinline__ void cp_commit() {
    asm volatile("cp.async.commit_group;" ::: "memory");
}
template <int N>
__device__ __forceinline__ void cp_wait() {
    asm volatile("cp.async.wait_group %0;" :: "n"(N) : "memory");
}

// split two fp32 into packed bf16 hi and lo words
__device__ __forceinline__ void split2(float x, float y, uint32_t& hi, uint32_t& lo) {
    __nv_bfloat16 hx = __float2bfloat16(x), hy = __float2bfloat16(y);
    __nv_bfloat16 lx = __float2bfloat16(x - __bfloat162float(hx));
    __nv_bfloat16 ly = __float2bfloat16(y - __bfloat162float(hy));
    hi = (uint32_t)__bfloat16_as_ushort(hx) | ((uint32_t)__bfloat16_as_ushort(hy) << 16);
    lo = (uint32_t)__bfloat16_as_ushort(lx) | ((uint32_t)__bfloat16_as_ushort(ly) << 16);
}

// ---------------------------------------------------------------------------
// fp32 -> (hi,lo) bf16 split. which: 0..2 = q/k/v inputs, 3..6 = Wq/Wk/Wv/Wo.
// ---------------------------------------------------------------------------
__global__ __launch_bounds__(256)
void cvt_hilo(const float* __restrict__ src, int which, int n4)
{
    __nv_bfloat16* hi;
    __nv_bfloat16* lo;
    if (which < 3) { hi = s_xh[which];     lo = s_xl[which]; }
    else           { hi = s_wh[which - 3]; lo = s_wl[which - 3]; }

    int i = blockIdx.x * blockDim.x + threadIdx.x;
    if (i >= n4) return;
    float4 v = ((const float4*)src)[i];
    float f[4] = {v.x, v.y, v.z, v.w};
    __nv_bfloat16 h[4], l[4];
#pragma unroll
    for (int j = 0; j < 4; j++) {
        h[j] = __float2bfloat16(f[j]);
        l[j] = __float2bfloat16(f[j] - __bfloat162float(h[j]));
    }
    ((uint2*)hi)[i] = *(uint2*)h;
    ((uint2*)lo)[i] = *(uint2*)l;
}

// ---------------------------------------------------------------------------
// HMMA GEMM: C[4096x1024] = X @ W^T (+bias), bf16 3-term compensation.
// mode 0: write bf16 hi/lo head-major [B,NH,S,D]; mode 1: fp32 row-major.
// ---------------------------------------------------------------------------
#define T_ROWB 80
#define TILE_B (128 * T_ROWB)
#define STAGE_B (4 * TILE_B)
#define GEMM_SMEM (2 * STAGE_B)     // 81920

__device__ __forceinline__ void stage_load(
    uint32_t smb, int buf, int k0,
    const __nv_bfloat16* Ah, const __nv_bfloat16* Al,
    const __nv_bfloat16* Bh, const __nv_bfloat16* Bl,
    int m0, int n0, int tid)
{
    const __nv_bfloat16* srcs[4] = {Ah, Al, Bh, Bl};
    const int rb[4] = {m0, m0, n0, n0};
    uint32_t sb = smb + buf * STAGE_B;
#pragma unroll
    for (int t = 0; t < 4; t++) {
#pragma unroll
        for (int i = 0; i < 2; i++) {
            int c = tid + i * 256;
            int r = c >> 2;
            int kc = c & 3;
            const void* g = srcs[t] + (size_t)(rb[t] + r) * 1024 + k0 + kc * 8;
            cp_async16(sb + t * TILE_B + r * T_ROWB + kc * 16, g);
        }
    }
}

__device__ __forceinline__ void gemm_hmma_body(
    const __nv_bfloat16* __restrict__ Ah, const __nv_bfloat16* __restrict__ Al,
    const __nv_bfloat16* __restrict__ Bh, const __nv_bfloat16* __restrict__ Bl,
    const float* __restrict__ bias, float* __restrict__ outp,
    __nv_bfloat16* __restrict__ outh, __nv_bfloat16* __restrict__ outl,
    int mode, uint8_t* dynsm)
{
    const uint32_t smb = smem_u32(dynsm);
    const int tid  = threadIdx.x;
    const int wid  = tid >> 5;
    const int lane = tid & 31;
    const int wm   = wid & 3;
    const int wn   = wid >> 2;
    const int m0   = blockIdx.x * 128;
    const int n0   = blockIdx.y * 128;

    float acc[2][8][4];
#pragma unroll
    for (int mt = 0; mt < 2; mt++)
#pragma unroll
        for (int nt = 0; nt < 8; nt++)
#pragma unroll
            for (int j = 0; j < 4; j++) acc[mt][nt][j] = 0.f;

    const int a_row = (lane & 15);
    const int a_col = (lane >> 4) * 16;
    const int b_row = (lane & 7) + ((lane >> 4) & 1) * 8;
    const int b_col = ((lane >> 3) & 1) * 16;

    stage_load(smb, 0, 0, Ah, Al, Bh, Bl, m0, n0, tid);
    cp_commit();

    const int NS = 1024 / 32;
    for (int s = 0; s < NS; s++) {
        if (s + 1 < NS) {
            stage_load(smb, (s + 1) & 1, (s + 1) * 32, Ah, Al, Bh, Bl, m0, n0, tid);
            cp_commit();
            cp_wait<1>();
        } else {
            cp_wait<0>();
        }
        __syncthreads();

        const uint32_t sb = smb + (s & 1) * STAGE_B;
        const uint32_t sAh = sb;
        const uint32_t sAl = sb + TILE_B;
        const uint32_t sBh = sb + 2 * TILE_B;
        const uint32_t sBl = sb + 3 * TILE_B;

#pragma unroll
        for (int kh = 0; kh < 2; kh++) {
            const int kb = kh * 32;
            uint32_t b[8][2];
#pragma unroll
            for (int p = 0; p < 4; p++) {
                uint32_t addr = sBh + (uint32_t)(wn * 64 + p * 16 + b_row) * T_ROWB + kb + b_col;
                ldsm_x4(b[2*p][0], b[2*p][1], b[2*p+1][0], b[2*p+1][1], addr);
            }
#pragma unroll
            for (int mt = 0; mt < 2; mt++) {
                uint32_t ah[4], al[4];
                uint32_t ra = (uint32_t)(wm * 32 + mt * 16 + a_row) * T_ROWB + kb + a_col;
                ldsm_x4(ah[0], ah[1], ah[2], ah[3], sAh + ra);
                ldsm_x4(al[0], al[1], al[2], al[3], sAl + ra);
#pragma unroll
                for (int nt = 0; nt < 8; nt++) {
                    mma16816(acc[mt][nt], ah[0], ah[1], ah[2], ah[3], b[nt][0], b[nt][1]);
                    mma16816(acc[mt][nt], al[0], al[1], al[2], al[3], b[nt][0], b[nt][1]);
                }
            }
#pragma unroll
            for (int p = 0; p < 4; p++) {
                uint32_t addr = sBl + (uint32_t)(wn * 64 + p * 16 + b_row) * T_ROWB + kb + b_col;
                ldsm_x4(b[2*p][0], b[2*p][1], b[2*p+1][0], b[2*p+1][1], addr);
            }
#pragma unroll
            for (int mt = 0; mt < 2; mt++) {
                uint32_t ah[4];
                uint32_t ra = (uint32_t)(wm * 32 + mt * 16 + a_row) * T_ROWB + kb + a_col;
                ldsm_x4(ah[0], ah[1], ah[2], ah[3], sAh + ra);
#pragma unroll
                for (int nt = 0; nt < 8; nt++)
                    mma16816(acc[mt][nt], ah[0], ah[1], ah[2], ah[3], b[nt][0], b[nt][1]);
            }
        }
        __syncthreads();
    }

    const int g  = lane >> 2;
    const int cq = (lane & 3) * 2;
#pragma unroll
    for (int mt = 0; mt < 2; mt++) {
#pragma unroll
        for (int nt = 0; nt < 8; nt++) {
            int col  = n0 + wn * 64 + nt * 8 + cq;
            int row0 = m0 + wm * 32 + mt * 16 + g;
            float bx = bias[col], by = bias[col + 1];
            float2 v0 = {acc[mt][nt][0] + bx, acc[mt][nt][1] + by};
            float2 v1 = {acc[mt][nt][2] + bx, acc[mt][nt][3] + by};
            if (mode == 0) {
                int bidx = row0 >> 9;
                int s0 = row0 & 511;
                int h = col >> 6, d = col & 63;
                size_t base = ((size_t)(bidx * NHh + h) * Ss) * Dd + d;
                uint32_t h0, l0, h1, l1;
                split2(v0.x, v0.y, h0, l0);
                split2(v1.x, v1.y, h1, l1);
                *(uint32_t*)&outh[base + (size_t)s0 * Dd] = h0;
                *(uint32_t*)&outl[base + (size_t)s0 * Dd] = l0;
                *(uint32_t*)&outh[base + (size_t)(s0 + 8) * Dd] = h1;
                *(uint32_t*)&outl[base + (size_t)(s0 + 8) * Dd] = l1;
            } else {
                *(float2*)&outp[(size_t)row0 * Hh + col] = v0;
                *(float2*)&outp[(size_t)(row0 + 8) * Hh + col] = v1;
            }
        }
    }
}

__global__ __launch_bounds__(256, 2)
void gemm_qkv_tc(const float* __restrict__ bq, const float* __restrict__ bk,
                 const float* __restrict__ bv)
{
    extern __shared__ uint8_t dynsm[];
    const int which = blockIdx.z;
    const float* bias = (which == 0) ? bq : (which == 1) ? bk : bv;
    __nv_bfloat16* oh = (which == 0) ? a_qh : (which == 1) ? a_kh : a_vh;
    __nv_bfloat16* ol = (which == 0) ? a_ql : (which == 1) ? a_kl : a_vl;
    gemm_hmma_body(s_xh[which], s_xl[which], s_wh[which], s_wl[which],
                   bias, nullptr, oh, ol, 0, dynsm);
}

__global__ __launch_bounds__(256, 2)
void gemm_out_tc(const float* __restrict__ bo, float* __restrict__ out)
{
    extern __shared__ uint8_t dynsm[];
    gemm_hmma_body(s_ah, s_al, s_wh[3], s_wl[3], bo, out, nullptr, nullptr, 1, dynsm);
}

// ---------------------------------------------------------------------------
// Tensor-core attention: block = (b, h, 32-q tile), 8 warps, 1 CTA/SM.
// QK^T (HMMA, 3-term) -> mask -> softmax+mod (fp32) -> P hi/lo -> PV (HMMA).
// ---------------------------------------------------------------------------
#define AQ_STR 144           // Q/K/V smem row stride (bytes)
#define ASC_STR 520          // score stride (floats)
#define AP_STR 520           // P stride (bf16)
#define AOFF_QH 0
#define AOFF_QL 4608
#define AOFF_KH 9216
#define AOFF_KL 46080        // 9216 + 256*144
#define AOFF_SC 82944        // 46080 + 36864
#define AOFF_PH 149504       // 82944 + 32*520*4
#define AOFF_PL 182784       // +32*520*2
#define AOFF_RED 216064      // +32*520*2
#define ATT_SMEM 224768      // +32*68*4

__global__ __launch_bounds__(256, 1)
void attn_tc(const float* __restrict__ mask,
             const int* __restrict__ lena,
             const float* __restrict__ kg,
             const float* __restrict__ hy,
             const int* __restrict__ layer_p)
{
    extern __shared__ uint8_t sm8[];
    const uint32_t smb = smem_u32(sm8);
    float* sc = (float*)(sm8 + AOFF_SC);
    __nv_bfloat16* PhP = (__nv_bfloat16*)(sm8 + AOFF_PH);
    __nv_bfloat16* PlP = (__nv_bfloat16*)(sm8 + AOFF_PL);
    float* red = (float*)(sm8 + AOFF_RED);

    const int bh = blockIdx.y;
    const int b  = bh >> 4;
    const int h  = bh & 15;
    const int q0 = blockIdx.x * 32;
    const int tid = threadIdx.x, wid = tid >> 5, lane = tid & 31;

    const int layer = layer_p[0];
    const float c0 = hy[layer * 3 + 0];
    const float c1 = hy[layer * 3 + 1];
    const float cc = hy[layer * 3 + 2];
    const int   l  = lena[b];

    const __nv_bfloat16* gQh = a_qh + (size_t)bh * Ss * Dd;
    const __nv_bfloat16* gQl = a_ql + (size_t)bh * Ss * Dd;
    const __nv_bfloat16* gKh = a_kh + (size_t)bh * Ss * Dd;
    const __nv_bfloat16* gKl = a_kl + (size_t)bh * Ss * Dd;
    const __nv_bfloat16* gVh = a_vh + (size_t)bh * Ss * Dd;
    const __nv_bfloat16* gVl = a_vl + (size_t)bh * Ss * Dd;

    // ---- load Q tile (32 x 64, hi+lo) ----
    {
        int q = tid >> 3, c = tid & 7;
        *(uint4*)(sm8 + AOFF_QH + q * AQ_STR + c * 16) =
            *(const uint4*)(gQh + (size_t)(q0 + q) * 64 + c * 8);
        *(uint4*)(sm8 + AOFF_QL + q * AQ_STR + c * 16) =
            *(const uint4*)(gQl + (size_t)(q0 + q) * 64 + c * 8);
    }

    const int a_row  = lane & 15;
    const int a_colb = (lane >> 4) * 16;
    const int b_row  = (lane & 7) + ((lane >> 4) & 1) * 8;
    const int b_colb = ((lane >> 3) & 1) * 16;
    const int g  = lane >> 2;
    const int cq = (lane & 3) * 2;

    // ---- QK^T: two passes over K halves ----
    for (int p = 0; p < 2; p++) {
        __syncthreads();
        for (int i = 0; i < 8; i++) {
            int idx = tid + i * 256;
            int r = idx >> 3, c = idx & 7;
            *(uint4*)(sm8 + AOFF_KH + r * AQ_STR + c * 16) =
                *(const uint4*)(gKh + (size_t)(p * 256 + r) * 64 + c * 8);
            *(uint4*)(sm8 + AOFF_KL + r * AQ_STR + c * 16) =
                *(const uint4*)(gKl + (size_t)(p * 256 + r) * 64 + c * 8);
        }
        __syncthreads();

        float acc[2][4][4];
#pragma unroll
        for (int mt = 0; mt < 2; mt++)
#pragma unroll
            for (int nt = 0; nt < 4; nt++)
#pragma unroll
                for (int j = 0; j < 4; j++) acc[mt][nt][j] = 0.f;

#pragma unroll
        for (int ks = 0; ks < 4; ks++) {
            int kb = ks * 32;
            uint32_t kbh[4][2], kbl[4][2];
#pragma unroll
            for (int pg = 0; pg < 2; pg++) {
                uint32_t ro = (uint32_t)(wid * 32 + pg * 16 + b_row) * AQ_STR + kb + b_colb;
                ldsm_x4(kbh[pg*2][0], kbh[pg*2][1], kbh[pg*2+1][0], kbh[pg*2+1][1],
                        smb + AOFF_KH + ro);
                ldsm_x4(kbl[pg*2][0], kbl[pg*2][1], kbl[pg*2+1][0], kbl[pg*2+1][1],
                        smb + AOFF_KL + ro);
            }
#pragma unroll
            for (int mt = 0; mt < 2; mt++) {
                uint32_t ra = (uint32_t)(mt * 16 + a_row) * AQ_STR + kb + a_colb;
                uint32_t ah[4], al[4];
                ldsm_x4(ah[0], ah[1], ah[2], ah[3], smb + AOFF_QH + ra);
                ldsm_x4(al[0], al[1], al[2], al[3], smb + AOFF_QL + ra);
#pragma unroll
                for (int nt = 0; nt < 4; nt++) {
                    mma16816(acc[mt][nt], ah[0], ah[1], ah[2], ah[3], kbh[nt][0], kbh[nt][1]);
                    mma16816(acc[mt][nt], al[0], al[1], al[2], al[3], kbh[nt][0], kbh[nt][1]);
                    mma16816(acc[mt][nt], ah[0], ah[1], ah[2], ah[3], kbl[nt][0], kbl[nt][1]);
                }
            }
        }
#pragma unroll
        for (int mt = 0; mt < 2; mt++)
#pragma unroll
            for (int nt = 0; nt < 4; nt++) {
                int row = mt * 16 + g;
                int col = p * 256 + wid * 32 + nt * 8 + cq;
                sc[row * ASC_STR + col]       = acc[mt][nt][0] * 0.125f;
                sc[row * ASC_STR + col + 1]   = acc[mt][nt][1] * 0.125f;
                sc[(row+8) * ASC_STR + col]   = acc[mt][nt][2] * 0.125f;
                sc[(row+8) * ASC_STR + col+1] = acc[mt][nt][3] * 0.125f;
            }
    }
    __syncthreads();

    // ---- mask add ----
    for (int idx = tid; idx < 32 * 512; idx += 256) {
        int q = idx >> 9, k = idx & 511;
        sc[q * ASC_STR + k] += mask[((size_t)b * Ss + (q0 + q)) * Ss + k];
    }
    __syncthreads();

    // ---- softmax + modification (writes final probs into sc) ----
    {
        const int row = tid >> 3;
        const int sub = tid & 7;
        float* rowp = &sc[row * ASC_STR];

        float mx = -1e30f;
        for (int k = sub; k < 512; k += 8) mx = fmaxf(mx, rowp[k]);
        mx = fmaxf(mx, __shfl_xor_sync(0xffffffffu, mx, 1));
        mx = fmaxf(mx, __shfl_xor_sync(0xffffffffu, mx, 2));
        mx = fmaxf(mx, __shfl_xor_sync(0xffffffffu, mx, 4));

        float sum = 0.f;
        for (int k = sub; k < 512; k += 8) {
            float e = __expf(rowp[k] - mx);
            rowp[k] = e;
            sum += e;
        }
        sum += __shfl_xor_sync(0xffffffffu, sum, 1);
        sum += __shfl_xor_sync(0xffffffffu, sum, 2);
        sum += __shfl_xor_sync(0xffffffffu, sum, 4);
        float inv = 1.f / sum;

        const int qg = q0 + row;
        const bool rowa_q = (qg >= 1) && (qg < l - 1);
        const bool cola_q = (qg >= l) && (qg < Ss - 1);
        const float* simp = &kg[(((size_t)b * 2 + 0) * Ss + qg) * Ss];
        const float* topp = &kg[(((size_t)b * 2 + 1) * Ss + qg) * Ss];
        for (int k = sub; k < 512; k += 8) {
            bool rowa_k = (k >= 1) && (k < l - 1);
            bool cola_k = (k >= l) && (k < Ss - 1);
            bool big = (rowa_q && cola_k) || (rowa_k && cola_q);
            float lf = big ? cc : 1.0f;
            rowp[k] = rowp[k] * inv * lf + c0 * simp[k] + c1 * topp[k];
        }
    }
    __syncthreads();

    // ---- convert P to bf16 hi/lo ----
    for (int i = 0; i < 32; i++) {
        int idx = (tid + i * 256) * 2;
        int q = idx >> 9, k = idx & 511;
        float2 v = *(float2*)&sc[q * ASC_STR + k];
        uint32_t hi, lo;
        split2(v.x, v.y, hi, lo);
        *(uint32_t*)&PhP[q * AP_STR + k] = hi;
        *(uint32_t*)&PlP[q * AP_STR + k] = lo;
    }

    // ---- PV: two passes over V halves, k-split across 4 warp pairs ----
    const int wk2 = wid >> 1, wm = wid & 1;
    float acc2[8][4];
#pragma unroll
    for (int nt = 0; nt < 8; nt++)
#pragma unroll
        for (int j = 0; j < 4; j++) acc2[nt][j] = 0.f;

    for (int p = 0; p < 2; p++) {
        __syncthreads();
        for (int i = 0; i < 8; i++) {
            int idx = tid + i * 256;
            int r = idx >> 3, c = idx & 7;
            *(uint4*)(sm8 + AOFF_KH + r * AQ_STR + c * 16) =
                *(const uint4*)(gVh + (size_t)(p * 256 + r) * 64 + c * 8);
            *(uint4*)(sm8 + AOFF_KL + r * AQ_STR + c * 16) =
                *(const uint4*)(gVl + (size_t)(p * 256 + r) * 64 + c * 8);
        }
        __syncthreads();

#pragma unroll
        for (int ks = 0; ks < 4; ks++) {
            int kwarp = wk2 * 64 + ks * 16;
            uint32_t ra = (uint32_t)(wm * 16 + a_row) * (AP_STR * 2)
                        + (uint32_t)(p * 256 + kwarp) * 2 + a_colb;
            uint32_t ph_[4], pl_[4];
            ldsm_x4(ph_[0], ph_[1], ph_[2], ph_[3], smb + AOFF_PH + ra);
            ldsm_x4(pl_[0], pl_[1], pl_[2], pl_[3], smb + AOFF_PL + ra);

            uint32_t vbh[8][2], vbl[8][2];
#pragma unroll
            for (int ng = 0; ng < 4; ng++) {
                uint32_t ad = (uint32_t)(kwarp + (lane & 15)) * AQ_STR
                            + (uint32_t)(ng * 16 + ((lane >> 4) & 1) * 8) * 2;
                ldsm_x4_t(vbh[ng*2][0], vbh[ng*2][1], vbh[ng*2+1][0], vbh[ng*2+1][1],
                          smb + AOFF_KH + ad);
                ldsm_x4_t(vbl[ng*2][0], vbl[ng*2][1], vbl[ng*2+1][0], vbl[ng*2+1][1],
                          smb + AOFF_KL + ad);
            }
#pragma unroll
            for (int nt = 0; nt < 8; nt++) {
                mma16816(acc2[nt], ph_[0], ph_[1], ph_[2], ph_[3], vbh[nt][0], vbh[nt][1]);
                mma16816(acc2[nt], pl_[0], pl_[1], pl_[2], pl_[3], vbh[nt][0], vbh[nt][1]);
                mma16816(acc2[nt], ph_[0], ph_[1], ph_[2], ph_[3], vbl[nt][0], vbl[nt][1]);
            }
        }
    }

    // ---- reduce k-partials across warp pairs ----
    for (int w = 0; w < 4; w++) {
        if (wk2 == w) {
#pragma unroll
            for (int nt = 0; nt < 8; nt++) {
                int row = wm * 16 + g;
                int col = nt * 8 + cq;
                if (w == 0) {
                    red[row * 68 + col]     = acc2[nt][0];
                    red[row * 68 + col + 1] = acc2[nt][1];
                    red[(row+8) * 68 + col]     = acc2[nt][2];
                    red[(row+8) * 68 + col + 1] = acc2[nt][3];
                } else {
                    red[row * 68 + col]     += acc2[nt][0];
                    red[row * 68 + col + 1] += acc2[nt][1];
                    red[(row+8) * 68 + col]     += acc2[nt][2];
                    red[(row+8) * 68 + col + 1] += acc2[nt][3];
                }
            }
        }
        __syncthreads();
    }

    // ---- write attention output as bf16 hi/lo [B,S,H] ----
    {
        int q = tid >> 3, c = tid & 7;
        float v[8];
#pragma unroll
        for (int j = 0; j < 8; j++) v[j] = red[q * 68 + c * 8 + j];
        uint32_t hw[4], lw[4];
#pragma unroll
        for (int j = 0; j < 4; j++) split2(v[2*j], v[2*j+1], hw[j], lw[j]);
        size_t base = ((size_t)(b * Ss + q0 + q)) * Hh + h * 64 + c * 8;
        uint4 uh = {hw[0], hw[1], hw[2], hw[3]};
        uint4 ul = {lw[0], lw[1], lw[2], lw[3]};
        *(uint4*)&s_ah[base] = uh;
        *(uint4*)&s_al[base] = ul;
    }
}

// ---------------------------------------------------------------------------
// Launch
// ---------------------------------------------------------------------------
extern "C" void kernel_launch(void* const* d_in, const int* in_sizes, int n_in,
                              void* d_out, int out_size)
{
    const float* q_in  = (const float*)d_in[0];
    const float* k_in  = (const float*)d_in[1];
    const float* v_in  = (const float*)d_in[2];
    const float* mask  = (const float*)d_in[3];
    const int*   lena  = (const int*)  d_in[4];
    const float* kg    = (const float*)d_in[5];
    const float* hy    = (const float*)d_in[6];
    const int*   layer = (const int*)  d_in[7];
    const float* Wq    = (const float*)d_in[8];
    const float* bq    = (const float*)d_in[9];
    const float* Wk    = (const float*)d_in[10];
    const float* bk    = (const float*)d_in[11];
    const float* Wv    = (const float*)d_in[12];
    const float* bv    = (const float*)d_in[13];
    const float* Wo    = (const float*)d_in[14];
    const float* bo    = (const float*)d_in[15];
    float* out = (float*)d_out;

    cudaFuncSetAttribute(gemm_qkv_tc, cudaFuncAttributeMaxDynamicSharedMemorySize, GEMM_SMEM);
    cudaFuncSetAttribute(gemm_out_tc, cudaFuncAttributeMaxDynamicSharedMemorySize, GEMM_SMEM);
    cudaFuncSetAttribute(attn_tc, cudaFuncAttributeMaxDynamicSharedMemorySize, ATT_SMEM);

    // Split inputs + weights to bf16 hi/lo
    {
        const int n4x = 4096 * 1024 / 4;
        cvt_hilo<<<n4x / 256, 256>>>(q_in, 0, n4x);
        cvt_hilo<<<n4x / 256, 256>>>(k_in, 1, n4x);
        cvt_hilo<<<n4x / 256, 256>>>(v_in, 2, n4x);
        const int n4w = 1024 * 1024 / 4;
        cvt_hilo<<<n4w / 256, 256>>>(Wq, 3, n4w);
        cvt_hilo<<<n4w / 256, 256>>>(Wk, 4, n4w);
        cvt_hilo<<<n4w / 256, 256>>>(Wv, 5, n4w);
        cvt_hilo<<<n4w / 256, 256>>>(Wo, 6, n4w);
    }

    // QKV projections (HMMA) -> bf16 hi/lo head-major
    {
        dim3 grid(4096 / 128, 1024 / 128, 3);
        gemm_qkv_tc<<<grid, 256, GEMM_SMEM>>>(bq, bk, bv);
    }

    // Attention (HMMA)
    {
        dim3 grid(Ss / 32, Bb * NHh, 1);
        attn_tc<<<grid, 256, ATT_SMEM>>>(mask, lena, kg, hy, layer);
    }

    // Output projection (HMMA)
    {
        dim3 grid(4096 / 128, 1024 / 128, 1);
        gemm_out_tc<<<grid, 256, GEMM_SMEM>>>(bo, out);
    }
}

// round 16
// speedup vs baseline: 1.8831x; 1.0301x over previous
#include <cuda_runtime.h>
#include <cuda_bf16.h>
#include <stdint.h>
#include <math.h>

#define Bb 8
#define Ss 512
#define Hh 1024
#define NHh 16
#define Dd 64

// ---------------------------------------------------------------------------
// Scratch (allocation-free rule: __device__ globals)
// ---------------------------------------------------------------------------
__device__ __nv_bfloat16 s_xh[3][4096*1024];   // q,k,v inputs
__device__ __nv_bfloat16 s_xl[3][4096*1024];
__device__ __nv_bfloat16 s_wh[4][1024*1024];   // Wq,Wk,Wv,Wo
__device__ __nv_bfloat16 s_wl[4][1024*1024];
__device__ __nv_bfloat16 a_qh[Bb*NHh*Ss*Dd];
__device__ __nv_bfloat16 a_ql[Bb*NHh*Ss*Dd];
__device__ __nv_bfloat16 a_kh[Bb*NHh*Ss*Dd];
__device__ __nv_bfloat16 a_kl[Bb*NHh*Ss*Dd];
__device__ __nv_bfloat16 a_vh[Bb*NHh*Ss*Dd];
__device__ __nv_bfloat16 a_vl[Bb*NHh*Ss*Dd];
__device__ __nv_bfloat16 s_ah[4096*1024];
__device__ __nv_bfloat16 s_al[4096*1024];

// ---------------------------------------------------------------------------
// Baseline-PTX tensor core helpers
// ---------------------------------------------------------------------------
__device__ __forceinline__ uint32_t smem_u32(const void* p) {
    uint32_t a;
    asm("{ .reg .u64 t; cvta.to.shared.u64 t, %1; cvt.u32.u64 %0, t; }" : "=r"(a) : "l"(p));
    return a;
}

__device__ __forceinline__ void mma16816(float* c,
    uint32_t a0, uint32_t a1, uint32_t a2, uint32_t a3,
    uint32_t b0, uint32_t b1)
{
    asm volatile(
        "mma.sync.aligned.m16n8k16.row.col.f32.bf16.bf16.f32 "
        "{%0,%1,%2,%3}, {%4,%5,%6,%7}, {%8,%9}, {%0,%1,%2,%3};"
        : "+f"(c[0]), "+f"(c[1]), "+f"(c[2]), "+f"(c[3])
        : "r"(a0), "r"(a1), "r"(a2), "r"(a3), "r"(b0), "r"(b1));
}

__device__ __forceinline__ void ldsm_x4(uint32_t& r0, uint32_t& r1,
                                        uint32_t& r2, uint32_t& r3, uint32_t addr)
{
    asm volatile("ldmatrix.sync.aligned.m8n8.x4.shared.b16 {%0,%1,%2,%3}, [%4];"
                 : "=r"(r0), "=r"(r1), "=r"(r2), "=r"(r3) : "r"(addr));
}

__device__ __forceinline__ void ldsm_x4_t(uint32_t& r0, uint32_t& r1,
                                          uint32_t& r2, uint32_t& r3, uint32_t addr)
{
    asm volatile("ldmatrix.sync.aligned.m8n8.x4.trans.shared.b16 {%0,%1,%2,%3}, [%4];"
                 : "=r"(r0), "=r"(r1), "=r"(r2), "=r"(r3) : "r"(addr));
}

__device__ __forceinline__ void cp_async16(uint32_t saddr, const void* gaddr) {
    asm volatile("cp.async.cg.shared.global [%0], [%1], 16;" :: "r"(saddr), "l"(gaddr));
}
__device__ __forceinline__ void cp_commit() {
    asm volatile("cp.async.commit_group;" ::: "memory");
}
template <int N>
__device__ __forceinline__ void cp_wait() {
    asm volatile("cp.async.wait_group %0;" :: "n"(N) : "memory");
}

__device__ __forceinline__ void split2(float x, float y, uint32_t& hi, uint32_t& lo) {
    __nv_bfloat16 hx = __float2bfloat16(x), hy = __float2bfloat16(y);
    __nv_bfloat16 lx = __float2bfloat16(x - __bfloat162float(hx));
    __nv_bfloat16 ly = __float2bfloat16(y - __bfloat162float(hy));
    hi = (uint32_t)__bfloat16_as_ushort(hx) | ((uint32_t)__bfloat16_as_ushort(hy) << 16);
    lo = (uint32_t)__bfloat16_as_ushort(lx) | ((uint32_t)__bfloat16_as_ushort(ly) << 16);
}

// ---------------------------------------------------------------------------
// fp32 -> (hi,lo) bf16 split kernels
// ---------------------------------------------------------------------------
__global__ __launch_bounds__(256)
void cvt_x(const float* __restrict__ src, int which, int n4)
{
    __nv_bfloat16* hi = s_xh[which];
    __nv_bfloat16* lo = s_xl[which];
    int i = blockIdx.x * blockDim.x + threadIdx.x;
    if (i >= n4) return;
    float4 v = ((const float4*)src)[i];
    float f[4] = {v.x, v.y, v.z, v.w};
    __nv_bfloat16 h[4], l[4];
#pragma unroll
    for (int j = 0; j < 4; j++) {
        h[j] = __float2bfloat16(f[j]);
        l[j] = __float2bfloat16(f[j] - __bfloat162float(h[j]));
    }
    ((uint2*)hi)[i] = *(uint2*)h;
    ((uint2*)lo)[i] = *(uint2*)l;
}

__global__ __launch_bounds__(256)
void cvt_w_all(const float* __restrict__ Wq, const float* __restrict__ Wk,
               const float* __restrict__ Wv, const float* __restrict__ Wo, int n4)
{
    int which = blockIdx.y;
    const float* src = (which == 0) ? Wq : (which == 1) ? Wk : (which == 2) ? Wv : Wo;
    __nv_bfloat16* hi = s_wh[which];
    __nv_bfloat16* lo = s_wl[which];
    int i = blockIdx.x * blockDim.x + threadIdx.x;
    if (i >= n4) return;
    float4 v = ((const float4*)src)[i];
    float f[4] = {v.x, v.y, v.z, v.w};
    __nv_bfloat16 h[4], l[4];
#pragma unroll
    for (int j = 0; j < 4; j++) {
        h[j] = __float2bfloat16(f[j]);
        l[j] = __float2bfloat16(f[j] - __bfloat162float(h[j]));
    }
    ((uint2*)hi)[i] = *(uint2*)h;
    ((uint2*)lo)[i] = *(uint2*)l;
}

// ---------------------------------------------------------------------------
// HMMA GEMM (unchanged from passing round-8 kernel)
// ---------------------------------------------------------------------------
#define T_ROWB 80
#define TILE_B (128 * T_ROWB)
#define STAGE_B (4 * TILE_B)
#define GEMM_SMEM (2 * STAGE_B)     // 81920

__device__ __forceinline__ void stage_load(
    uint32_t smb, int buf, int k0,
    const __nv_bfloat16* Ah, const __nv_bfloat16* Al,
    const __nv_bfloat16* Bh, const __nv_bfloat16* Bl,
    int m0, int n0, int tid)
{
    const __nv_bfloat16* srcs[4] = {Ah, Al, Bh, Bl};
    const int rb[4] = {m0, m0, n0, n0};
    uint32_t sb = smb + buf * STAGE_B;
#pragma unroll
    for (int t = 0; t < 4; t++) {
#pragma unroll
        for (int i = 0; i < 2; i++) {
            int c = tid + i * 256;
            int r = c >> 2;
            int kc = c & 3;
            const void* g = srcs[t] + (size_t)(rb[t] + r) * 1024 + k0 + kc * 8;
            cp_async16(sb + t * TILE_B + r * T_ROWB + kc * 16, g);
        }
    }
}

__device__ __forceinline__ void gemm_hmma_body(
    const __nv_bfloat16* __restrict__ Ah, const __nv_bfloat16* __restrict__ Al,
    const __nv_bfloat16* __restrict__ Bh, const __nv_bfloat16* __restrict__ Bl,
    const float* __restrict__ bias, float* __restrict__ outp,
    __nv_bfloat16* __restrict__ outh, __nv_bfloat16* __restrict__ outl,
    int mode, uint8_t* dynsm)
{
    const uint32_t smb = smem_u32(dynsm);
    const int tid  = threadIdx.x;
    const int wid  = tid >> 5;
    const int lane = tid & 31;
    const int wm   = wid & 3;
    const int wn   = wid >> 2;
    const int m0   = blockIdx.x * 128;
    const int n0   = blockIdx.y * 128;

    float acc[2][8][4];
#pragma unroll
    for (int mt = 0; mt < 2; mt++)
#pragma unroll
        for (int nt = 0; nt < 8; nt++)
#pragma unroll
            for (int j = 0; j < 4; j++) acc[mt][nt][j] = 0.f;

    const int a_row = (lane & 15);
    const int a_col = (lane >> 4) * 16;
    const int b_row = (lane & 7) + ((lane >> 4) & 1) * 8;
    const int b_col = ((lane >> 3) & 1) * 16;

    stage_load(smb, 0, 0, Ah, Al, Bh, Bl, m0, n0, tid);
    cp_commit();

    const int NS = 1024 / 32;
    for (int s = 0; s < NS; s++) {
        if (s + 1 < NS) {
            stage_load(smb, (s + 1) & 1, (s + 1) * 32, Ah, Al, Bh, Bl, m0, n0, tid);
            cp_commit();
            cp_wait<1>();
        } else {
            cp_wait<0>();
        }
        __syncthreads();

        const uint32_t sb = smb + (s & 1) * STAGE_B;
        const uint32_t sAh = sb;
        const uint32_t sAl = sb + TILE_B;
        const uint32_t sBh = sb + 2 * TILE_B;
        const uint32_t sBl = sb + 3 * TILE_B;

#pragma unroll
        for (int kh = 0; kh < 2; kh++) {
            const int kb = kh * 32;
            uint32_t b[8][2];
#pragma unroll
            for (int p = 0; p < 4; p++) {
                uint32_t addr = sBh + (uint32_t)(wn * 64 + p * 16 + b_row) * T_ROWB + kb + b_col;
                ldsm_x4(b[2*p][0], b[2*p][1], b[2*p+1][0], b[2*p+1][1], addr);
            }
#pragma unroll
            for (int mt = 0; mt < 2; mt++) {
                uint32_t ah[4], al[4];
                uint32_t ra = (uint32_t)(wm * 32 + mt * 16 + a_row) * T_ROWB + kb + a_col;
                ldsm_x4(ah[0], ah[1], ah[2], ah[3], sAh + ra);
                ldsm_x4(al[0], al[1], al[2], al[3], sAl + ra);
#pragma unroll
                for (int nt = 0; nt < 8; nt++) {
                    mma16816(acc[mt][nt], ah[0], ah[1], ah[2], ah[3], b[nt][0], b[nt][1]);
                    mma16816(acc[mt][nt], al[0], al[1], al[2], al[3], b[nt][0], b[nt][1]);
                }
            }
#pragma unroll
            for (int p = 0; p < 4; p++) {
                uint32_t addr = sBl + (uint32_t)(wn * 64 + p * 16 + b_row) * T_ROWB + kb + b_col;
                ldsm_x4(b[2*p][0], b[2*p][1], b[2*p+1][0], b[2*p+1][1], addr);
            }
#pragma unroll
            for (int mt = 0; mt < 2; mt++) {
                uint32_t ah[4];
                uint32_t ra = (uint32_t)(wm * 32 + mt * 16 + a_row) * T_ROWB + kb + a_col;
                ldsm_x4(ah[0], ah[1], ah[2], ah[3], sAh + ra);
#pragma unroll
                for (int nt = 0; nt < 8; nt++)
                    mma16816(acc[mt][nt], ah[0], ah[1], ah[2], ah[3], b[nt][0], b[nt][1]);
            }
        }
        __syncthreads();
    }

    const int g  = lane >> 2;
    const int cq = (lane & 3) * 2;
#pragma unroll
    for (int mt = 0; mt < 2; mt++) {
#pragma unroll
        for (int nt = 0; nt < 8; nt++) {
            int col  = n0 + wn * 64 + nt * 8 + cq;
            int row0 = m0 + wm * 32 + mt * 16 + g;
            float bx = bias[col], by = bias[col + 1];
            float2 v0 = {acc[mt][nt][0] + bx, acc[mt][nt][1] + by};
            float2 v1 = {acc[mt][nt][2] + bx, acc[mt][nt][3] + by};
            if (mode == 0) {
                int bidx = row0 >> 9;
                int s0 = row0 & 511;
                int h = col >> 6, d = col & 63;
                size_t base = ((size_t)(bidx * NHh + h) * Ss) * Dd + d;
                uint32_t h0, l0, h1, l1;
                split2(v0.x, v0.y, h0, l0);
                split2(v1.x, v1.y, h1, l1);
                *(uint32_t*)&outh[base + (size_t)s0 * Dd] = h0;
                *(uint32_t*)&outl[base + (size_t)s0 * Dd] = l0;
                *(uint32_t*)&outh[base + (size_t)(s0 + 8) * Dd] = h1;
                *(uint32_t*)&outl[base + (size_t)(s0 + 8) * Dd] = l1;
            } else {
                *(float2*)&outp[(size_t)row0 * Hh + col] = v0;
                *(float2*)&outp[(size_t)(row0 + 8) * Hh + col] = v1;
            }
        }
    }
}

__global__ __launch_bounds__(256, 2)
void gemm_qkv_tc(const float* __restrict__ bq, const float* __restrict__ bk,
                 const float* __restrict__ bv)
{
    extern __shared__ uint8_t dynsm[];
    const int which = blockIdx.z;
    const float* bias = (which == 0) ? bq : (which == 1) ? bk : bv;
    __nv_bfloat16* oh = (which == 0) ? a_qh : (which == 1) ? a_kh : a_vh;
    __nv_bfloat16* ol = (which == 0) ? a_ql : (which == 1) ? a_kl : a_vl;
    gemm_hmma_body(s_xh[which], s_xl[which], s_wh[which], s_wl[which],
                   bias, nullptr, oh, ol, 0, dynsm);
}

__global__ __launch_bounds__(256, 2)
void gemm_out_tc(const float* __restrict__ bo, float* __restrict__ out)
{
    extern __shared__ uint8_t dynsm[];
    gemm_hmma_body(s_ah, s_al, s_wh[3], s_wl[3], bo, out, nullptr, nullptr, 1, dynsm);
}

// ---------------------------------------------------------------------------
// Tensor-core attention: fused mask+softmax+mod+P-split, parallel reduction.
// ---------------------------------------------------------------------------
#define AQ_STR 144
#define ASC_STR 520
#define AP_STR 520
#define AOFF_QH 0
#define AOFF_QL 4608
#define AOFF_KH 9216
#define AOFF_KL 46080
#define AOFF_SC 82944
#define AOFF_PH 149504
#define AOFF_PL 182784
#define ATT_SMEM 216064

__global__ __launch_bounds__(256, 1)
void attn_tc(const float* __restrict__ mask,
             const int* __restrict__ lena,
             const float* __restrict__ kg,
             const float* __restrict__ hy,
             const int* __restrict__ layer_p)
{
    extern __shared__ uint8_t sm8[];
    const uint32_t smb = smem_u32(sm8);
    float* sc = (float*)(sm8 + AOFF_SC);
    __nv_bfloat16* PhP = (__nv_bfloat16*)(sm8 + AOFF_PH);
    __nv_bfloat16* PlP = (__nv_bfloat16*)(sm8 + AOFF_PL);

    const int bh = blockIdx.y;
    const int b  = bh >> 4;
    const int h  = bh & 15;
    const int q0 = blockIdx.x * 32;
    const int tid = threadIdx.x, wid = tid >> 5, lane = tid & 31;

    const int layer = layer_p[0];
    const float c0 = hy[layer * 3 + 0];
    const float c1 = hy[layer * 3 + 1];
    const float cc = hy[layer * 3 + 2];
    const int   l  = lena[b];

    const __nv_bfloat16* gQh = a_qh + (size_t)bh * Ss * Dd;
    const __nv_bfloat16* gQl = a_ql + (size_t)bh * Ss * Dd;
    const __nv_bfloat16* gKh = a_kh + (size_t)bh * Ss * Dd;
    const __nv_bfloat16* gKl = a_kl + (size_t)bh * Ss * Dd;
    const __nv_bfloat16* gVh = a_vh + (size_t)bh * Ss * Dd;
    const __nv_bfloat16* gVl = a_vl + (size_t)bh * Ss * Dd;

    // ---- load Q tile (32 x 64, hi+lo) ----
    {
        int q = tid >> 3, c = tid & 7;
        *(uint4*)(sm8 + AOFF_QH + q * AQ_STR + c * 16) =
            *(const uint4*)(gQh + (size_t)(q0 + q) * 64 + c * 8);
        *(uint4*)(sm8 + AOFF_QL + q * AQ_STR + c * 16) =
            *(const uint4*)(gQl + (size_t)(q0 + q) * 64 + c * 8);
    }

    const int a_row  = lane & 15;
    const int a_colb = (lane >> 4) * 16;
    const int b_row  = (lane & 7) + ((lane >> 4) & 1) * 8;
    const int b_colb = ((lane >> 3) & 1) * 16;
    const int g  = lane >> 2;
    const int cq = (lane & 3) * 2;

    // ---- QK^T: two passes over K halves ----
    for (int p = 0; p < 2; p++) {
        __syncthreads();
        for (int i = 0; i < 8; i++) {
            int idx = tid + i * 256;
            int r = idx >> 3, c = idx & 7;
            *(uint4*)(sm8 + AOFF_KH + r * AQ_STR + c * 16) =
                *(const uint4*)(gKh + (size_t)(p * 256 + r) * 64 + c * 8);
            *(uint4*)(sm8 + AOFF_KL + r * AQ_STR + c * 16) =
                *(const uint4*)(gKl + (size_t)(p * 256 + r) * 64 + c * 8);
        }
        __syncthreads();

        float acc[2][4][4];
#pragma unroll
        for (int mt = 0; mt < 2; mt++)
#pragma unroll
            for (int nt = 0; nt < 4; nt++)
#pragma unroll
                for (int j = 0; j < 4; j++) acc[mt][nt][j] = 0.f;

#pragma unroll
        for (int ks = 0; ks < 4; ks++) {
            int kb = ks * 32;
            uint32_t kbh[4][2], kbl[4][2];
#pragma unroll
            for (int pg = 0; pg < 2; pg++) {
                uint32_t ro = (uint32_t)(wid * 32 + pg * 16 + b_row) * AQ_STR + kb + b_colb;
                ldsm_x4(kbh[pg*2][0], kbh[pg*2][1], kbh[pg*2+1][0], kbh[pg*2+1][1],
                        smb + AOFF_KH + ro);
                ldsm_x4(kbl[pg*2][0], kbl[pg*2][1], kbl[pg*2+1][0], kbl[pg*2+1][1],
                        smb + AOFF_KL + ro);
            }
#pragma unroll
            for (int mt = 0; mt < 2; mt++) {
                uint32_t ra = (uint32_t)(mt * 16 + a_row) * AQ_STR + kb + a_colb;
                uint32_t ah[4], al[4];
                ldsm_x4(ah[0], ah[1], ah[2], ah[3], smb + AOFF_QH + ra);
                ldsm_x4(al[0], al[1], al[2], al[3], smb + AOFF_QL + ra);
#pragma unroll
                for (int nt = 0; nt < 4; nt++) {
                    mma16816(acc[mt][nt], ah[0], ah[1], ah[2], ah[3], kbh[nt][0], kbh[nt][1]);
                    mma16816(acc[mt][nt], al[0], al[1], al[2], al[3], kbh[nt][0], kbh[nt][1]);
                    mma16816(acc[mt][nt], ah[0], ah[1], ah[2], ah[3], kbl[nt][0], kbl[nt][1]);
                }
            }
        }
#pragma unroll
        for (int mt = 0; mt < 2; mt++)
#pragma unroll
            for (int nt = 0; nt < 4; nt++) {
                int row = mt * 16 + g;
                int col = p * 256 + wid * 32 + nt * 8 + cq;
                sc[row * ASC_STR + col]       = acc[mt][nt][0] * 0.125f;
                sc[row * ASC_STR + col + 1]   = acc[mt][nt][1] * 0.125f;
                sc[(row+8) * ASC_STR + col]   = acc[mt][nt][2] * 0.125f;
                sc[(row+8) * ASC_STR + col+1] = acc[mt][nt][3] * 0.125f;
            }
    }
    __syncthreads();

    // ---- fused: mask add + softmax + modification + P hi/lo split ----
    {
        const int row = tid >> 3;
        const int sub = tid & 7;
        float* rowp = &sc[row * ASC_STR];
        const int qg = q0 + row;
        const float* maskp = &mask[((size_t)b * Ss + qg) * Ss];

        float mx = -1e30f;
        for (int k = sub; k < 512; k += 8) {
            float v = rowp[k] + maskp[k];
            rowp[k] = v;
            mx = fmaxf(mx, v);
        }
        mx = fmaxf(mx, __shfl_xor_sync(0xffffffffu, mx, 1));
        mx = fmaxf(mx, __shfl_xor_sync(0xffffffffu, mx, 2));
        mx = fmaxf(mx, __shfl_xor_sync(0xffffffffu, mx, 4));

        float sum = 0.f;
        for (int k = sub; k < 512; k += 8) {
            float e = __expf(rowp[k] - mx);
            rowp[k] = e;
            sum += e;
        }
        sum += __shfl_xor_sync(0xffffffffu, sum, 1);
        sum += __shfl_xor_sync(0xffffffffu, sum, 2);
        sum += __shfl_xor_sync(0xffffffffu, sum, 4);
        float inv = 1.f / sum;

        const bool rowa_q = (qg >= 1) && (qg < l - 1);
        const bool cola_q = (qg >= l) && (qg < Ss - 1);
        const float* simp = &kg[(((size_t)b * 2 + 0) * Ss + qg) * Ss];
        const float* topp = &kg[(((size_t)b * 2 + 1) * Ss + qg) * Ss];
        __nv_bfloat16* PhR = PhP + row * AP_STR;
        __nv_bfloat16* PlR = PlP + row * AP_STR;
        for (int k = sub; k < 512; k += 8) {
            bool rowa_k = (k >= 1) && (k < l - 1);
            bool cola_k = (k >= l) && (k < Ss - 1);
            bool big = (rowa_q && cola_k) || (rowa_k && cola_q);
            float lf = big ? cc : 1.0f;
            float pf = rowp[k] * inv * lf + c0 * simp[k] + c1 * topp[k];
            __nv_bfloat16 hb = __float2bfloat16(pf);
            PhR[k] = hb;
            PlR[k] = __float2bfloat16(pf - __bfloat162float(hb));
        }
    }
    __syncthreads();

    // ---- PV: two passes over V halves, k-split across 4 warp pairs ----
    const int wk2 = wid >> 1, wm = wid & 1;
    float acc2[8][4];
#pragma unroll
    for (int nt = 0; nt < 8; nt++)
#pragma unroll
        for (int j = 0; j < 4; j++) acc2[nt][j] = 0.f;

    for (int p = 0; p < 2; p++) {
        if (p) __syncthreads();
        for (int i = 0; i < 8; i++) {
            int idx = tid + i * 256;
            int r = idx >> 3, c = idx & 7;
            *(uint4*)(sm8 + AOFF_KH + r * AQ_STR + c * 16) =
                *(const uint4*)(gVh + (size_t)(p * 256 + r) * 64 + c * 8);
            *(uint4*)(sm8 + AOFF_KL + r * AQ_STR + c * 16) =
                *(const uint4*)(gVl + (size_t)(p * 256 + r) * 64 + c * 8);
        }
        __syncthreads();

#pragma unroll
        for (int ks = 0; ks < 4; ks++) {
            int kwarp = wk2 * 64 + ks * 16;
            uint32_t ra = (uint32_t)(wm * 16 + a_row) * (AP_STR * 2)
                        + (uint32_t)(p * 256 + kwarp) * 2 + a_colb;
            uint32_t ph_[4], pl_[4];
            ldsm_x4(ph_[0], ph_[1], ph_[2], ph_[3], smb + AOFF_PH + ra);
            ldsm_x4(pl_[0], pl_[1], pl_[2], pl_[3], smb + AOFF_PL + ra);

            uint32_t vbh[8][2], vbl[8][2];
#pragma unroll
            for (int ng = 0; ng < 4; ng++) {
                uint32_t ad = (uint32_t)(kwarp + (lane & 15)) * AQ_STR
                            + (uint32_t)(ng * 16 + ((lane >> 4) & 1) * 8) * 2;
                ldsm_x4_t(vbh[ng*2][0], vbh[ng*2][1], vbh[ng*2+1][0], vbh[ng*2+1][1],
                          smb + AOFF_KH + ad);
                ldsm_x4_t(vbl[ng*2][0], vbl[ng*2][1], vbl[ng*2+1][0], vbl[ng*2+1][1],
                          smb + AOFF_KL + ad);
            }
#pragma unroll
            for (int nt = 0; nt < 8; nt++) {
                mma16816(acc2[nt], ph_[0], ph_[1], ph_[2], ph_[3], vbh[nt][0], vbh[nt][1]);
                mma16816(acc2[nt], pl_[0], pl_[1], pl_[2], pl_[3], vbh[nt][0], vbh[nt][1]);
                mma16816(acc2[nt], ph_[0], ph_[1], ph_[2], ph_[3], vbl[nt][0], vbl[nt][1]);
            }
        }
    }

    // ---- parallel reduction of k-partials (V region is dead now) ----
    float* part = (float*)(sm8 + AOFF_KH);   // 4 * 32*68 * 4B = 34816 B
    __syncthreads();
    {
        int base = wk2 * (32 * 68);
#pragma unroll
        for (int nt = 0; nt < 8; nt++) {
            int row = wm * 16 + g;
            int col = nt * 8 + cq;
            part[base + row * 68 + col]         = acc2[nt][0];
            part[base + row * 68 + col + 1]     = acc2[nt][1];
            part[base + (row + 8) * 68 + col]   = acc2[nt][2];
            part[base + (row + 8) * 68 + col+1] = acc2[nt][3];
        }
    }
    __syncthreads();

    // ---- sum partials + write attention output as bf16 hi/lo [B,S,H] ----
    {
        int q = tid >> 3, c = tid & 7;
        float v[8];
#pragma unroll
        for (int j = 0; j < 8; j++) {
            int o = q * 68 + c * 8 + j;
            v[j] = part[o] + part[2176 + o] + part[2*2176 + o] + part[3*2176 + o];
        }
        uint32_t hw[4], lw[4];
#pragma unroll
        for (int j = 0; j < 4; j++) split2(v[2*j], v[2*j+1], hw[j], lw[j]);
        size_t base = ((size_t)(b * Ss + q0 + q)) * Hh + h * 64 + c * 8;
        uint4 uh = {hw[0], hw[1], hw[2], hw[3]};
        uint4 ul = {lw[0], lw[1], lw[2], lw[3]};
        *(uint4*)&s_ah[base] = uh;
        *(uint4*)&s_al[base] = ul;
    }
}

// ---------------------------------------------------------------------------
// Launch — attn_tc is launch index 5 so the fixed ncu -s 5 window captures it.
// ---------------------------------------------------------------------------
extern "C" void kernel_launch(void* const* d_in, const int* in_sizes, int n_in,
                              void* d_out, int out_size)
{
    const float* q_in  = (const float*)d_in[0];
    const float* k_in  = (const float*)d_in[1];
    const float* v_in  = (const float*)d_in[2];
    const float* mask  = (const float*)d_in[3];
    const int*   lena  = (const int*)  d_in[4];
    const float* kg    = (const float*)d_in[5];
    const float* hy    = (const float*)d_in[6];
    const int*   layer = (const int*)  d_in[7];
    const float* Wq    = (const float*)d_in[8];
    const float* bq    = (const float*)d_in[9];
    const float* Wk    = (const float*)d_in[10];
    const float* bk    = (const float*)d_in[11];
    const float* Wv    = (const float*)d_in[12];
    const float* bv    = (const float*)d_in[13];
    const float* Wo    = (const float*)d_in[14];
    const float* bo    = (const float*)d_in[15];
    float* out = (float*)d_out;

    cudaFuncSetAttribute(gemm_qkv_tc, cudaFuncAttributeMaxDynamicSharedMemorySize, GEMM_SMEM);
    cudaFuncSetAttribute(gemm_out_tc, cudaFuncAttributeMaxDynamicSharedMemorySize, GEMM_SMEM);
    cudaFuncSetAttribute(attn_tc, cudaFuncAttributeMaxDynamicSharedMemorySize, ATT_SMEM);

    const int n4x = 4096 * 1024 / 4;
    const int n4w = 1024 * 1024 / 4;

    cvt_x<<<n4x / 256, 256>>>(q_in, 0, n4x);                    // launch 0
    cvt_x<<<n4x / 256, 256>>>(k_in, 1, n4x);                    // launch 1
    cvt_x<<<n4x / 256, 256>>>(v_in, 2, n4x);                    // launch 2
    {
        dim3 gw(n4w / 256, 4);
        cvt_w_all<<<gw, 256>>>(Wq, Wk, Wv, Wo, n4w);            // launch 3
    }
    {
        dim3 grid(4096 / 128, 1024 / 128, 3);
        gemm_qkv_tc<<<grid, 256, GEMM_SMEM>>>(bq, bk, bv);      // launch 4
    }
    {
        dim3 grid(Ss / 32, Bb * NHh, 1);
        attn_tc<<<grid, 256, ATT_SMEM>>>(mask, lena, kg, hy, layer);  // launch 5 (ncu)
    }
    {
        dim3 grid(4096 / 128, 1024 / 128, 1);
        gemm_out_tc<<<grid, 256, GEMM_SMEM>>>(bo, out);         // launch 6
    }
}

// round 17
// speedup vs baseline: 2.0158x; 1.0705x over previous
#include <cuda_runtime.h>
#include <cuda_bf16.h>
#include <stdint.h>
#include <math.h>

#define Bb 8
#define Ss 512
#define Hh 1024
#define NHh 16
#define Dd 64

// ---------------------------------------------------------------------------
// Scratch (allocation-free rule: __device__ globals)
// ---------------------------------------------------------------------------
__device__ __nv_bfloat16 s_xh[3][4096*1024];   // q,k,v inputs
__device__ __nv_bfloat16 s_xl[3][4096*1024];
__device__ __nv_bfloat16 s_wh[4][1024*1024];   // Wq,Wk,Wv,Wo
__device__ __nv_bfloat16 s_wl[4][1024*1024];
__device__ __nv_bfloat16 a_qh[Bb*NHh*Ss*Dd];
__device__ __nv_bfloat16 a_ql[Bb*NHh*Ss*Dd];
__device__ __nv_bfloat16 a_kh[Bb*NHh*Ss*Dd];
__device__ __nv_bfloat16 a_kl[Bb*NHh*Ss*Dd];
__device__ __nv_bfloat16 a_vh[Bb*NHh*Ss*Dd];
__device__ __nv_bfloat16 a_vl[Bb*NHh*Ss*Dd];
__device__ __nv_bfloat16 s_ah[4096*1024];
__device__ __nv_bfloat16 s_al[4096*1024];

// ---------------------------------------------------------------------------
// Baseline-PTX tensor core helpers
// ---------------------------------------------------------------------------
__device__ __forceinline__ uint32_t smem_u32(const void* p) {
    uint32_t a;
    asm("{ .reg .u64 t; cvta.to.shared.u64 t, %1; cvt.u32.u64 %0, t; }" : "=r"(a) : "l"(p));
    return a;
}

__device__ __forceinline__ void mma16816(float* c,
    uint32_t a0, uint32_t a1, uint32_t a2, uint32_t a3,
    uint32_t b0, uint32_t b1)
{
    asm volatile(
        "mma.sync.aligned.m16n8k16.row.col.f32.bf16.bf16.f32 "
        "{%0,%1,%2,%3}, {%4,%5,%6,%7}, {%8,%9}, {%0,%1,%2,%3};"
        : "+f"(c[0]), "+f"(c[1]), "+f"(c[2]), "+f"(c[3])
        : "r"(a0), "r"(a1), "r"(a2), "r"(a3), "r"(b0), "r"(b1));
}

__device__ __forceinline__ void ldsm_x4(uint32_t& r0, uint32_t& r1,
                                        uint32_t& r2, uint32_t& r3, uint32_t addr)
{
    asm volatile("ldmatrix.sync.aligned.m8n8.x4.shared.b16 {%0,%1,%2,%3}, [%4];"
                 : "=r"(r0), "=r"(r1), "=r"(r2), "=r"(r3) : "r"(addr));
}

__device__ __forceinline__ void ldsm_x4_t(uint32_t& r0, uint32_t& r1,
                                          uint32_t& r2, uint32_t& r3, uint32_t addr)
{
    asm volatile("ldmatrix.sync.aligned.m8n8.x4.trans.shared.b16 {%0,%1,%2,%3}, [%4];"
                 : "=r"(r0), "=r"(r1), "=r"(r2), "=r"(r3) : "r"(addr));
}

__device__ __forceinline__ void cp_async16(uint32_t saddr, const void* gaddr) {
    asm volatile("cp.async.cg.shared.global [%0], [%1], 16;" :: "r"(saddr), "l"(gaddr));
}
__device__ __forceinline__ void cp_commit() {
    asm volatile("cp.async.commit_group;" ::: "memory");
}
template <int N>
__device__ __forceinline__ void cp_wait() {
    asm volatile("cp.async.wait_group %0;" :: "n"(N) : "memory");
}

__device__ __forceinline__ void split2(float x, float y, uint32_t& hi, uint32_t& lo) {
    __nv_bfloat16 hx = __float2bfloat16(x), hy = __float2bfloat16(y);
    __nv_bfloat16 lx = __float2bfloat16(x - __bfloat162float(hx));
    __nv_bfloat16 ly = __float2bfloat16(y - __bfloat162float(hy));
    hi = (uint32_t)__bfloat16_as_ushort(hx) | ((uint32_t)__bfloat16_as_ushort(hy) << 16);
    lo = (uint32_t)__bfloat16_as_ushort(lx) | ((uint32_t)__bfloat16_as_ushort(ly) << 16);
}

// ---------------------------------------------------------------------------
// fp32 -> (hi,lo) bf16 split kernels
// ---------------------------------------------------------------------------
__global__ __launch_bounds__(256)
void cvt_x_all(const float* __restrict__ q_in, const float* __restrict__ k_in,
               const float* __restrict__ v_in, int n4)
{
    int which = blockIdx.y;
    const float* src = (which == 0) ? q_in : (which == 1) ? k_in : v_in;
    __nv_bfloat16* hi = s_xh[which];
    __nv_bfloat16* lo = s_xl[which];
    int i = blockIdx.x * blockDim.x + threadIdx.x;
    if (i >= n4) return;
    float4 v = ((const float4*)src)[i];
    float f[4] = {v.x, v.y, v.z, v.w};
    __nv_bfloat16 h[4], l[4];
#pragma unroll
    for (int j = 0; j < 4; j++) {
        h[j] = __float2bfloat16(f[j]);
        l[j] = __float2bfloat16(f[j] - __bfloat162float(h[j]));
    }
    ((uint2*)hi)[i] = *(uint2*)h;
    ((uint2*)lo)[i] = *(uint2*)l;
}

__global__ __launch_bounds__(256)
void cvt_w_all(const float* __restrict__ Wq, const float* __restrict__ Wk,
               const float* __restrict__ Wv, const float* __restrict__ Wo, int n4)
{
    int which = blockIdx.y;
    const float* src = (which == 0) ? Wq : (which == 1) ? Wk : (which == 2) ? Wv : Wo;
    __nv_bfloat16* hi = s_wh[which];
    __nv_bfloat16* lo = s_wl[which];
    int i = blockIdx.x * blockDim.x + threadIdx.x;
    if (i >= n4) return;
    float4 v = ((const float4*)src)[i];
    float f[4] = {v.x, v.y, v.z, v.w};
    __nv_bfloat16 h[4], l[4];
#pragma unroll
    for (int j = 0; j < 4; j++) {
        h[j] = __float2bfloat16(f[j]);
        l[j] = __float2bfloat16(f[j] - __bfloat162float(h[j]));
    }
    ((uint2*)hi)[i] = *(uint2*)h;
    ((uint2*)lo)[i] = *(uint2*)l;
}

// ---------------------------------------------------------------------------
// HMMA GEMM (unchanged from passing round-8/16 kernel)
// ---------------------------------------------------------------------------
#define T_ROWB 80
#define TILE_B (128 * T_ROWB)
#define STAGE_B (4 * TILE_B)
#define GEMM_SMEM (2 * STAGE_B)     // 81920

__device__ __forceinline__ void stage_load(
    uint32_t smb, int buf, int k0,
    const __nv_bfloat16* Ah, const __nv_bfloat16* Al,
    const __nv_bfloat16* Bh, const __nv_bfloat16* Bl,
    int m0, int n0, int tid)
{
    const __nv_bfloat16* srcs[4] = {Ah, Al, Bh, Bl};
    const int rb[4] = {m0, m0, n0, n0};
    uint32_t sb = smb + buf * STAGE_B;
#pragma unroll
    for (int t = 0; t < 4; t++) {
#pragma unroll
        for (int i = 0; i < 2; i++) {
            int c = tid + i * 256;
            int r = c >> 2;
            int kc = c & 3;
            const void* g = srcs[t] + (size_t)(rb[t] + r) * 1024 + k0 + kc * 8;
            cp_async16(sb + t * TILE_B + r * T_ROWB + kc * 16, g);
        }
    }
}

__device__ __forceinline__ void gemm_hmma_body(
    const __nv_bfloat16* __restrict__ Ah, const __nv_bfloat16* __restrict__ Al,
    const __nv_bfloat16* __restrict__ Bh, const __nv_bfloat16* __restrict__ Bl,
    const float* __restrict__ bias, float* __restrict__ outp,
    __nv_bfloat16* __restrict__ outh, __nv_bfloat16* __restrict__ outl,
    int mode, uint8_t* dynsm)
{
    const uint32_t smb = smem_u32(dynsm);
    const int tid  = threadIdx.x;
    const int wid  = tid >> 5;
    const int lane = tid & 31;
    const int wm   = wid & 3;
    const int wn   = wid >> 2;
    const int m0   = blockIdx.x * 128;
    const int n0   = blockIdx.y * 128;

    float acc[2][8][4];
#pragma unroll
    for (int mt = 0; mt < 2; mt++)
#pragma unroll
        for (int nt = 0; nt < 8; nt++)
#pragma unroll
            for (int j = 0; j < 4; j++) acc[mt][nt][j] = 0.f;

    const int a_row = (lane & 15);
    const int a_col = (lane >> 4) * 16;
    const int b_row = (lane & 7) + ((lane >> 4) & 1) * 8;
    const int b_col = ((lane >> 3) & 1) * 16;

    stage_load(smb, 0, 0, Ah, Al, Bh, Bl, m0, n0, tid);
    cp_commit();

    const int NS = 1024 / 32;
    for (int s = 0; s < NS; s++) {
        if (s + 1 < NS) {
            stage_load(smb, (s + 1) & 1, (s + 1) * 32, Ah, Al, Bh, Bl, m0, n0, tid);
            cp_commit();
            cp_wait<1>();
        } else {
            cp_wait<0>();
        }
        __syncthreads();

        const uint32_t sb = smb + (s & 1) * STAGE_B;
        const uint32_t sAh = sb;
        const uint32_t sAl = sb + TILE_B;
        const uint32_t sBh = sb + 2 * TILE_B;
        const uint32_t sBl = sb + 3 * TILE_B;

#pragma unroll
        for (int kh = 0; kh < 2; kh++) {
            const int kb = kh * 32;
            uint32_t b[8][2];
#pragma unroll
            for (int p = 0; p < 4; p++) {
                uint32_t addr = sBh + (uint32_t)(wn * 64 + p * 16 + b_row) * T_ROWB + kb + b_col;
                ldsm_x4(b[2*p][0], b[2*p][1], b[2*p+1][0], b[2*p+1][1], addr);
            }
#pragma unroll
            for (int mt = 0; mt < 2; mt++) {
                uint32_t ah[4], al[4];
                uint32_t ra = (uint32_t)(wm * 32 + mt * 16 + a_row) * T_ROWB + kb + a_col;
                ldsm_x4(ah[0], ah[1], ah[2], ah[3], sAh + ra);
                ldsm_x4(al[0], al[1], al[2], al[3], sAl + ra);
#pragma unroll
                for (int nt = 0; nt < 8; nt++) {
                    mma16816(acc[mt][nt], ah[0], ah[1], ah[2], ah[3], b[nt][0], b[nt][1]);
                    mma16816(acc[mt][nt], al[0], al[1], al[2], al[3], b[nt][0], b[nt][1]);
                }
            }
#pragma unroll
            for (int p = 0; p < 4; p++) {
                uint32_t addr = sBl + (uint32_t)(wn * 64 + p * 16 + b_row) * T_ROWB + kb + b_col;
                ldsm_x4(b[2*p][0], b[2*p][1], b[2*p+1][0], b[2*p+1][1], addr);
            }
#pragma unroll
            for (int mt = 0; mt < 2; mt++) {
                uint32_t ah[4];
                uint32_t ra = (uint32_t)(wm * 32 + mt * 16 + a_row) * T_ROWB + kb + a_col;
                ldsm_x4(ah[0], ah[1], ah[2], ah[3], sAh + ra);
#pragma unroll
                for (int nt = 0; nt < 8; nt++)
                    mma16816(acc[mt][nt], ah[0], ah[1], ah[2], ah[3], b[nt][0], b[nt][1]);
            }
        }
        __syncthreads();
    }

    const int g  = lane >> 2;
    const int cq = (lane & 3) * 2;
#pragma unroll
    for (int mt = 0; mt < 2; mt++) {
#pragma unroll
        for (int nt = 0; nt < 8; nt++) {
            int col  = n0 + wn * 64 + nt * 8 + cq;
            int row0 = m0 + wm * 32 + mt * 16 + g;
            float bx = bias[col], by = bias[col + 1];
            float2 v0 = {acc[mt][nt][0] + bx, acc[mt][nt][1] + by};
            float2 v1 = {acc[mt][nt][2] + bx, acc[mt][nt][3] + by};
            if (mode == 0) {
                int bidx = row0 >> 9;
                int s0 = row0 & 511;
                int h = col >> 6, d = col & 63;
                size_t base = ((size_t)(bidx * NHh + h) * Ss) * Dd + d;
                uint32_t h0, l0, h1, l1;
                split2(v0.x, v0.y, h0, l0);
                split2(v1.x, v1.y, h1, l1);
                *(uint32_t*)&outh[base + (size_t)s0 * Dd] = h0;
                *(uint32_t*)&outl[base + (size_t)s0 * Dd] = l0;
                *(uint32_t*)&outh[base + (size_t)(s0 + 8) * Dd] = h1;
                *(uint32_t*)&outl[base + (size_t)(s0 + 8) * Dd] = l1;
            } else {
                *(float2*)&outp[(size_t)row0 * Hh + col] = v0;
                *(float2*)&outp[(size_t)(row0 + 8) * Hh + col] = v1;
            }
        }
    }
}

__global__ __launch_bounds__(256, 2)
void gemm_qkv_tc(const float* __restrict__ bq, const float* __restrict__ bk,
                 const float* __restrict__ bv)
{
    extern __shared__ uint8_t dynsm[];
    const int which = blockIdx.z;
    const float* bias = (which == 0) ? bq : (which == 1) ? bk : bv;
    __nv_bfloat16* oh = (which == 0) ? a_qh : (which == 1) ? a_kh : a_vh;
    __nv_bfloat16* ol = (which == 0) ? a_ql : (which == 1) ? a_kl : a_vl;
    gemm_hmma_body(s_xh[which], s_xl[which], s_wh[which], s_wl[which],
                   bias, nullptr, oh, ol, 0, dynsm);
}

__global__ __launch_bounds__(256, 2)
void gemm_out_tc(const float* __restrict__ bo, float* __restrict__ out)
{
    extern __shared__ uint8_t dynsm[];
    gemm_hmma_body(s_ah, s_al, s_wh[3], s_wl[3], bo, out, nullptr, nullptr, 1, dynsm);
}

// ---------------------------------------------------------------------------
// Tensor-core attention, q-tile = 16 rows, 2 CTAs/SM.
// Regions: sc[0,33280) Q[33280,42496) KV[42496,79360) P[79360,112640)
// ---------------------------------------------------------------------------
#define AQ_STR 144
#define ASC_STR 520          // fp32 stride
#define AP_STR 520           // bf16 stride
#define AOFF_SC 0
#define AOFF_QH 33280
#define AOFF_QL 37888
#define AOFF_KH 42496
#define AOFF_KL 60928        // +128*144
#define AOFF_PH 79360
#define AOFF_PL 96000        // +16*520*2
#define ATT_SMEM 112640

__global__ __launch_bounds__(256, 2)
void attn_tc(const float* __restrict__ mask,
             const int* __restrict__ lena,
             const float* __restrict__ kg,
             const float* __restrict__ hy,
             const int* __restrict__ layer_p)
{
    extern __shared__ uint8_t sm8[];
    const uint32_t smb = smem_u32(sm8);
    float* sc = (float*)(sm8 + AOFF_SC);
    __nv_bfloat16* PhP = (__nv_bfloat16*)(sm8 + AOFF_PH);
    __nv_bfloat16* PlP = (__nv_bfloat16*)(sm8 + AOFF_PL);

    const int bh = blockIdx.y;
    const int b  = bh >> 4;
    const int h  = bh & 15;
    const int q0 = blockIdx.x * 16;
    const int tid = threadIdx.x, wid = tid >> 5, lane = tid & 31;

    const int layer = layer_p[0];
    const float c0 = hy[layer * 3 + 0];
    const float c1 = hy[layer * 3 + 1];
    const float cc = hy[layer * 3 + 2];
    const int   l  = lena[b];

    const __nv_bfloat16* gQh = a_qh + (size_t)bh * Ss * Dd;
    const __nv_bfloat16* gQl = a_ql + (size_t)bh * Ss * Dd;
    const __nv_bfloat16* gKh = a_kh + (size_t)bh * Ss * Dd;
    const __nv_bfloat16* gKl = a_kl + (size_t)bh * Ss * Dd;
    const __nv_bfloat16* gVh = a_vh + (size_t)bh * Ss * Dd;
    const __nv_bfloat16* gVl = a_vl + (size_t)bh * Ss * Dd;

    // ---- load Q tile (16 x 64, hi+lo) ----
    if (tid < 128) {
        int q = tid >> 3, c = tid & 7;
        *(uint4*)(sm8 + AOFF_QH + q * AQ_STR + c * 16) =
            *(const uint4*)(gQh + (size_t)(q0 + q) * 64 + c * 8);
        *(uint4*)(sm8 + AOFF_QL + q * AQ_STR + c * 16) =
            *(const uint4*)(gQl + (size_t)(q0 + q) * 64 + c * 8);
    }

    const int a_row  = lane & 15;
    const int a_colb = (lane >> 4) * 16;
    const int b_row  = (lane & 7) + ((lane >> 4) & 1) * 8;
    const int b_colb = ((lane >> 3) & 1) * 16;
    const int g  = lane >> 2;
    const int cq = (lane & 3) * 2;

    // ---- QK^T: 4 passes over 128-row K tiles ----
    for (int p = 0; p < 4; p++) {
        __syncthreads();
#pragma unroll
        for (int i = 0; i < 4; i++) {
            int idx = tid + i * 256;
            int r = idx >> 3, c = idx & 7;
            *(uint4*)(sm8 + AOFF_KH + r * AQ_STR + c * 16) =
                *(const uint4*)(gKh + (size_t)(p * 128 + r) * 64 + c * 8);
            *(uint4*)(sm8 + AOFF_KL + r * AQ_STR + c * 16) =
                *(const uint4*)(gKl + (size_t)(p * 128 + r) * 64 + c * 8);
        }
        __syncthreads();

        float acc[2][4];
#pragma unroll
        for (int nt = 0; nt < 2; nt++)
#pragma unroll
            for (int j = 0; j < 4; j++) acc[nt][j] = 0.f;

#pragma unroll
        for (int ks = 0; ks < 4; ks++) {
            int kb = ks * 32;
            uint32_t kbh[2][2], kbl[2][2];
            uint32_t ro = (uint32_t)(wid * 16 + b_row) * AQ_STR + kb + b_colb;
            ldsm_x4(kbh[0][0], kbh[0][1], kbh[1][0], kbh[1][1], smb + AOFF_KH + ro);
            ldsm_x4(kbl[0][0], kbl[0][1], kbl[1][0], kbl[1][1], smb + AOFF_KL + ro);

            uint32_t ra = (uint32_t)a_row * AQ_STR + kb + a_colb;
            uint32_t ah[4], al[4];
            ldsm_x4(ah[0], ah[1], ah[2], ah[3], smb + AOFF_QH + ra);
            ldsm_x4(al[0], al[1], al[2], al[3], smb + AOFF_QL + ra);
#pragma unroll
            for (int nt = 0; nt < 2; nt++) {
                mma16816(acc[nt], ah[0], ah[1], ah[2], ah[3], kbh[nt][0], kbh[nt][1]);
                mma16816(acc[nt], al[0], al[1], al[2], al[3], kbh[nt][0], kbh[nt][1]);
                mma16816(acc[nt], ah[0], ah[1], ah[2], ah[3], kbl[nt][0], kbl[nt][1]);
            }
        }
#pragma unroll
        for (int nt = 0; nt < 2; nt++) {
            int col = p * 128 + wid * 16 + nt * 8 + cq;
            sc[g * ASC_STR + col]       = acc[nt][0] * 0.125f;
            sc[g * ASC_STR + col + 1]   = acc[nt][1] * 0.125f;
            sc[(g+8) * ASC_STR + col]   = acc[nt][2] * 0.125f;
            sc[(g+8) * ASC_STR + col+1] = acc[nt][3] * 0.125f;
        }
    }
    __syncthreads();

    // ---- fused: mask add + softmax + modification + P hi/lo split ----
    {
        const int row = tid >> 4;        // 0..15
        const int sub = tid & 15;
        float* rowp = &sc[row * ASC_STR];
        const int qg = q0 + row;
        const float* maskp = &mask[((size_t)b * Ss + qg) * Ss];

        float mx = -1e30f;
        for (int k = sub; k < 512; k += 16) {
            float v = rowp[k] + maskp[k];
            rowp[k] = v;
            mx = fmaxf(mx, v);
        }
        mx = fmaxf(mx, __shfl_xor_sync(0xffffffffu, mx, 1));
        mx = fmaxf(mx, __shfl_xor_sync(0xffffffffu, mx, 2));
        mx = fmaxf(mx, __shfl_xor_sync(0xffffffffu, mx, 4));
        mx = fmaxf(mx, __shfl_xor_sync(0xffffffffu, mx, 8));

        float sum = 0.f;
        for (int k = sub; k < 512; k += 16) {
            float e = __expf(rowp[k] - mx);
            rowp[k] = e;
            sum += e;
        }
        sum += __shfl_xor_sync(0xffffffffu, sum, 1);
        sum += __shfl_xor_sync(0xffffffffu, sum, 2);
        sum += __shfl_xor_sync(0xffffffffu, sum, 4);
        sum += __shfl_xor_sync(0xffffffffu, sum, 8);
        float inv = 1.f / sum;

        const bool rowa_q = (qg >= 1) && (qg < l - 1);
        const bool cola_q = (qg >= l) && (qg < Ss - 1);
        const float* simp = &kg[(((size_t)b * 2 + 0) * Ss + qg) * Ss];
        const float* topp = &kg[(((size_t)b * 2 + 1) * Ss + qg) * Ss];
        __nv_bfloat16* PhR = PhP + row * AP_STR;
        __nv_bfloat16* PlR = PlP + row * AP_STR;
        for (int k = sub; k < 512; k += 16) {
            bool rowa_k = (k >= 1) && (k < l - 1);
            bool cola_k = (k >= l) && (k < Ss - 1);
            bool big = (rowa_q && cola_k) || (rowa_k && cola_q);
            float lf = big ? cc : 1.0f;
            float pf = rowp[k] * inv * lf + c0 * simp[k] + c1 * topp[k];
            __nv_bfloat16 hb = __float2bfloat16(pf);
            PhR[k] = hb;
            PlR[k] = __float2bfloat16(pf - __bfloat162float(hb));
        }
    }

    // ---- PV: 4 passes over 128-row V tiles; warp wid owns 16 k per pass ----
    float acc2[8][4];
#pragma unroll
    for (int nt = 0; nt < 8; nt++)
#pragma unroll
        for (int j = 0; j < 4; j++) acc2[nt][j] = 0.f;

    for (int p = 0; p < 4; p++) {
        __syncthreads();   // fences softmax P writes (p=0) / prior MMA V reads (p>0)
#pragma unroll
        for (int i = 0; i < 4; i++) {
            int idx = tid + i * 256;
            int r = idx >> 3, c = idx & 7;
            *(uint4*)(sm8 + AOFF_KH + r * AQ_STR + c * 16) =
                *(const uint4*)(gVh + (size_t)(p * 128 + r) * 64 + c * 8);
            *(uint4*)(sm8 + AOFF_KL + r * AQ_STR + c * 16) =
                *(const uint4*)(gVl + (size_t)(p * 128 + r) * 64 + c * 8);
        }
        __syncthreads();

        {
            int kwarp = wid * 16;   // warp's k-slice within the 128-row tile
            uint32_t ra = (uint32_t)a_row * (AP_STR * 2)
                        + (uint32_t)(p * 128 + kwarp) * 2 + a_colb;
            uint32_t ph_[4], pl_[4];
            ldsm_x4(ph_[0], ph_[1], ph_[2], ph_[3], smb + AOFF_PH + ra);
            ldsm_x4(pl_[0], pl_[1], pl_[2], pl_[3], smb + AOFF_PL + ra);

            uint32_t vbh[8][2], vbl[8][2];
#pragma unroll
            for (int ng = 0; ng < 4; ng++) {
                uint32_t ad = (uint32_t)(kwarp + (lane & 15)) * AQ_STR
                            + (uint32_t)(ng * 16 + ((lane >> 4) & 1) * 8) * 2;
                ldsm_x4_t(vbh[ng*2][0], vbh[ng*2][1], vbh[ng*2+1][0], vbh[ng*2+1][1],
                          smb + AOFF_KH + ad);
                ldsm_x4_t(vbl[ng*2][0], vbl[ng*2][1], vbl[ng*2+1][0], vbl[ng*2+1][1],
                          smb + AOFF_KL + ad);
            }
#pragma unroll
            for (int nt = 0; nt < 8; nt++) {
                mma16816(acc2[nt], ph_[0], ph_[1], ph_[2], ph_[3], vbh[nt][0], vbh[nt][1]);
                mma16816(acc2[nt], pl_[0], pl_[1], pl_[2], pl_[3], vbh[nt][0], vbh[nt][1]);
                mma16816(acc2[nt], ph_[0], ph_[1], ph_[2], ph_[3], vbl[nt][0], vbl[nt][1]);
            }
        }
    }

    // ---- parallel reduction of 8 k-partials (P region is dead now) ----
    float* part = (float*)(sm8 + AOFF_PH);   // 8 * 16*64 * 4B = 32768 <= 33280
    __syncthreads();
    {
        int base = wid * (16 * 64);
#pragma unroll
        for (int nt = 0; nt < 8; nt++) {
            int col = nt * 8 + cq;
            part[base + g * 64 + col]         = acc2[nt][0];
            part[base + g * 64 + col + 1]     = acc2[nt][1];
            part[base + (g + 8) * 64 + col]   = acc2[nt][2];
            part[base + (g + 8) * 64 + col+1] = acc2[nt][3];
        }
    }
    __syncthreads();

    // ---- sum partials + write attention output as bf16 hi/lo [B,S,H] ----
    {
        int q = tid >> 4, c = (tid & 15) * 4;
        float v[4];
#pragma unroll
        for (int j = 0; j < 4; j++) {
            int o = q * 64 + c + j;
            float s = 0.f;
#pragma unroll
            for (int w = 0; w < 8; w++) s += part[w * 1024 + o];
            v[j] = s;
        }
        uint32_t hw[2], lw[2];
        split2(v[0], v[1], hw[0], lw[0]);
        split2(v[2], v[3], hw[1], lw[1]);
        size_t base = ((size_t)(b * Ss + q0 + q)) * Hh + h * 64 + c;
        uint2 uh = {hw[0], hw[1]};
        uint2 ul = {lw[0], lw[1]};
        *(uint2*)&s_ah[base] = uh;
        *(uint2*)&s_al[base] = ul;
    }
}

// ---------------------------------------------------------------------------
// Launch
// ---------------------------------------------------------------------------
extern "C" void kernel_launch(void* const* d_in, const int* in_sizes, int n_in,
                              void* d_out, int out_size)
{
    const float* q_in  = (const float*)d_in[0];
    const float* k_in  = (const float*)d_in[1];
    const float* v_in  = (const float*)d_in[2];
    const float* mask  = (const float*)d_in[3];
    const int*   lena  = (const int*)  d_in[4];
    const float* kg    = (const float*)d_in[5];
    const float* hy    = (const float*)d_in[6];
    const int*   layer = (const int*)  d_in[7];
    const float* Wq    = (const float*)d_in[8];
    const float* bq    = (const float*)d_in[9];
    const float* Wk    = (const float*)d_in[10];
    const float* bk    = (const float*)d_in[11];
    const float* Wv    = (const float*)d_in[12];
    const float* bv    = (const float*)d_in[13];
    const float* Wo    = (const float*)d_in[14];
    const float* bo    = (const float*)d_in[15];
    float* out = (float*)d_out;

    cudaFuncSetAttribute(gemm_qkv_tc, cudaFuncAttributeMaxDynamicSharedMemorySize, GEMM_SMEM);
    cudaFuncSetAttribute(gemm_out_tc, cudaFuncAttributeMaxDynamicSharedMemorySize, GEMM_SMEM);
    cudaFuncSetAttribute(attn_tc, cudaFuncAttributeMaxDynamicSharedMemorySize, ATT_SMEM);

    const int n4x = 4096 * 1024 / 4;
    const int n4w = 1024 * 1024 / 4;

    {
        dim3 gx(n4x / 256, 3);
        cvt_x_all<<<gx, 256>>>(q_in, k_in, v_in, n4x);
    }
    {
        dim3 gw(n4w / 256, 4);
        cvt_w_all<<<gw, 256>>>(Wq, Wk, Wv, Wo, n4w);
    }
    {
        dim3 grid(4096 / 128, 1024 / 128, 3);
        gemm_qkv_tc<<<grid, 256, GEMM_SMEM>>>(bq, bk, bv);
    }
    {
        dim3 grid(Ss / 16, Bb * NHh, 1);
        attn_tc<<<grid, 256, ATT_SMEM>>>(mask, lena, kg, hy, layer);
    }
    {
        dim3 grid(4096 / 128, 1024 / 128, 1);
        gemm_out_tc<<<grid, 256, GEMM_SMEM>>>(bo, out);
    }
}